// round 9
// baseline (speedup 1.0000x reference)
#include <cuda_runtime.h>
#include <math.h>

// Problem dims
#define C_   3
#define T_   100
#define B_   512
#define F_   128
#define HX_  128
#define HZ_  128
#define H_   256
#define EH_  128
#define L_   64

#define NB_   86   // CTAs per channel (86*6=516 >= 512; 258 CTAs, 1 wave @ 2/SM)
#define RMAX_ 6    // rows per CTA

// ---- big activations scratch ----
__device__ float g_PI[(size_t)C_ * T_ * B_ * H_];   // x@WxI + bihq2
__device__ float g_PO[(size_t)C_ * T_ * B_ * F_];   // x@WxO + bo3
__device__ float g_Hs[(size_t)C_ * T_ * B_ * H_];   // h at step input

// ---- folded weights (computed on-device each run; tiny) ----
__device__ float g_Weq[C_ * HX_ * L_];    // We_x @ Wqm              [128,64]/ch
__device__ float g_beq[C_ * L_];          // be@Wqm + bqm
__device__ float g_Wcomb[C_ * H_ * L_];   // We_h @ Wqm              [256,64]/ch
__device__ float g_Wihz[L_ * H_];         // Wzp @ Wih_z             [64,256]
__device__ float g_bihz[H_];              // bzp @ Wih_z
__device__ float g_Wdz[C_ * L_ * EH_];    // Wzp @ Wd_z              [64,128]/ch
__device__ float g_bdz[C_ * EH_];         // bzp@Wd_z + bd
__device__ float g_Wzo[C_ * L_ * F_];     // Wdz @ Wpm               [64,128]/ch
__device__ float g_Who[C_ * H_ * F_];     // Wd_h @ Wpm              [256,128]/ch
__device__ float g_bo[C_ * F_];           // bdz@Wpm + bpm
__device__ float g_Whh2[C_ * H_ * H_];    // Whh + Wcomb@Wihz        [256,256]/ch
__device__ float g_Wihq[C_ * HX_ * H_];   // Wih_x + Weq@Wihz        [128,256]/ch
__device__ float g_bihq[C_ * H_];         // bih+bhh+bihz + beq@Wihz
__device__ float g_Who2[C_ * H_ * F_];    // Who + Wcomb@Wzo         [256,128]/ch
__device__ float g_Wxo[C_ * HX_ * F_];    // Weq @ Wzo               [128,128]/ch
__device__ float g_bo2[C_ * F_];          // beq@Wzo + bo
__device__ float g_WxI[C_ * F_ * H_];     // Wx @ Wihq               [128,256]/ch
__device__ float g_bihq2[C_ * H_];        // bx@Wihq + bihq
__device__ float g_WxO[C_ * F_ * F_];     // Wx @ Wxo                [128,128]/ch
__device__ float g_bo3[C_ * F_];          // bx@Wxo + bo2

// ===========================================================================
// small generic GEMM for weight folding: out = A[M,K]@Bm[K,N] (+ addm)
// ===========================================================================
__device__ __forceinline__ void small_gemmK(const float* __restrict__ A, int lda,
                                            const float* __restrict__ Bm, int ldb,
                                            float* __restrict__ out, int M, int N,
                                            int K, const float* __restrict__ addm,
                                            int ldam) {
    for (int idx = threadIdx.x; idx < M * N; idx += 256) {
        const int m = idx / N, n = idx % N;
        float s = addm ? addm[(size_t)m * ldam + n] : 0.f;
        const float* a = A + (size_t)m * lda;
        const float* b = Bm + n;
#pragma unroll 4
        for (int k = 0; k < K; ++k) s = fmaf(a[k], b[(size_t)k * ldb], s);
        out[idx] = s;
    }
}

// fold stage 1: products of raw inputs (29 CTAs)
__global__ void __launch_bounds__(256) kernelF1(
    const float* __restrict__ We, const float* __restrict__ be,
    const float* __restrict__ Wqm, const float* __restrict__ bqm,
    const float* __restrict__ Wzp, const float* __restrict__ bzp,
    const float* __restrict__ Wd, const float* __restrict__ bd,
    const float* __restrict__ Wih) {
    const int t = blockIdx.x;
    if (t < 6) {                       // Weq blocks (M=64)
        const int c = t >> 1, rb = t & 1;
        small_gemmK(We + (size_t)c * 384 * EH_ + rb * 64 * EH_, EH_,
                    Wqm + (size_t)c * EH_ * L_, L_,
                    g_Weq + c * HX_ * L_ + rb * 64 * L_, 64, L_, EH_, nullptr, 0);
    } else if (t < 18) {               // Wcomb blocks
        const int u = t - 6, c = u >> 2, rb = u & 3;
        small_gemmK(We + (size_t)c * 384 * EH_ + (128 + rb * 64) * EH_, EH_,
                    Wqm + (size_t)c * EH_ * L_, L_,
                    g_Wcomb + c * H_ * L_ + rb * 64 * L_, 64, L_, EH_, nullptr, 0);
    } else if (t < 21) {               // Wdz = Wzp @ Wd_z
        const int c = t - 18;
        small_gemmK(Wzp, HZ_, Wd + (size_t)c * 384 * EH_, EH_,
                    g_Wdz + c * L_ * EH_, L_, EH_, HZ_, nullptr, 0);
    } else if (t == 21) {              // Wihz = Wzp @ Wih_z
        small_gemmK(Wzp, HZ_, Wih + 128 * H_, H_, g_Wihz, L_, H_, HZ_, nullptr, 0);
    } else if (t < 25) {               // beq = be@Wqm + bqm
        const int c = t - 22;
        small_gemmK(be + c * EH_, EH_, Wqm + (size_t)c * EH_ * L_, L_,
                    g_beq + c * L_, 1, L_, EH_, bqm + c * L_, 0);
    } else if (t < 28) {               // bdz = bzp@Wd_z + bd
        const int c = t - 25;
        small_gemmK(bzp, HZ_, Wd + (size_t)c * 384 * EH_, EH_,
                    g_bdz + c * EH_, 1, EH_, HZ_, bd + c * EH_, 0);
    } else {                           // bihz = bzp@Wih_z
        small_gemmK(bzp, HZ_, Wih + 128 * H_, H_, g_bihz, 1, H_, HZ_, nullptr, 0);
    }
}

// fold stage 2: products involving fold-1 outputs (39 CTAs)
__global__ void __launch_bounds__(256) kernelF2(
    const float* __restrict__ Wd, const float* __restrict__ Wpm,
    const float* __restrict__ bpm, const float* __restrict__ Whh,
    const float* __restrict__ Wih, const float* __restrict__ bih,
    const float* __restrict__ bhh) {
    const int t = blockIdx.x;
    if (t < 3) {                       // Wzo = Wdz @ Wpm
        const int c = t;
        small_gemmK(g_Wdz + c * L_ * EH_, EH_, Wpm + (size_t)c * EH_ * F_, F_,
                    g_Wzo + c * L_ * F_, L_, F_, EH_, nullptr, 0);
    } else if (t < 15) {               // Who = Wd_h @ Wpm
        const int u = t - 3, c = u >> 2, rb = u & 3;
        small_gemmK(Wd + (size_t)c * 384 * EH_ + (128 + rb * 64) * EH_, EH_,
                    Wpm + (size_t)c * EH_ * F_, F_,
                    g_Who + c * H_ * F_ + rb * 64 * F_, 64, F_, EH_, nullptr, 0);
    } else if (t < 18) {               // bo = bdz@Wpm + bpm
        const int c = t - 15;
        small_gemmK(g_bdz + c * EH_, EH_, Wpm + (size_t)c * EH_ * F_, F_,
                    g_bo + c * F_, 1, F_, EH_, bpm + c * F_, 0);
    } else if (t < 30) {               // Whh2 = Whh + Wcomb @ Wihz (K=64)
        const int u = t - 18, c = u >> 2, mb = u & 3;
        small_gemmK(g_Wcomb + c * H_ * L_ + mb * 64 * L_, L_,
                    g_Wihz, H_,
                    g_Whh2 + (size_t)c * H_ * H_ + mb * 64 * H_, 64, H_, L_,
                    Whh + (size_t)mb * 64 * H_, H_);
    } else if (t < 36) {               // Wihq = Wih_x + Weq @ Wihz (K=64)
        const int u = t - 30, c = u >> 1, mb = u & 1;
        small_gemmK(g_Weq + c * HX_ * L_ + mb * 64 * L_, L_,
                    g_Wihz, H_,
                    g_Wihq + (size_t)c * HX_ * H_ + mb * 64 * H_, 64, H_, L_,
                    Wih + (size_t)mb * 64 * H_, H_);
    } else {                           // bihq = bih+bhh+bihz + beq@Wihz
        const int c = t - 36;
        for (int n = threadIdx.x; n < H_; n += 256) {
            float s = bih[n] + bhh[n] + g_bihz[n];
            for (int l = 0; l < L_; ++l)
                s = fmaf(g_beq[c * L_ + l], g_Wihz[l * H_ + n], s);
            g_bihq[c * H_ + n] = s;
        }
    }
}

// fold stage 3: output-path folds (21 CTAs)
__global__ void __launch_bounds__(256) kernelF3() {
    const int t = blockIdx.x;
    if (t < 12) {                      // Who2 = Who + Wcomb @ Wzo (K=64)
        const int c = t >> 2, mb = t & 3;
        small_gemmK(g_Wcomb + c * H_ * L_ + mb * 64 * L_, L_,
                    g_Wzo + c * L_ * F_, F_,
                    g_Who2 + c * H_ * F_ + mb * 64 * F_, 64, F_, L_,
                    g_Who + c * H_ * F_ + mb * 64 * F_, F_);
    } else if (t < 18) {               // Wxo = Weq @ Wzo (K=64)
        const int u = t - 12, c = u >> 1, mb = u & 1;
        small_gemmK(g_Weq + c * HX_ * L_ + mb * 64 * L_, L_,
                    g_Wzo + c * L_ * F_, F_,
                    g_Wxo + c * HX_ * F_ + mb * 64 * F_, 64, F_, L_, nullptr, 0);
    } else {                           // bo2 = beq@Wzo + bo
        const int c = t - 18;
        small_gemmK(g_beq + c * L_, L_, g_Wzo + c * L_ * F_, F_,
                    g_bo2 + c * F_, 1, F_, L_, g_bo + c * F_, 0);
    }
}

// fold stage 4: fold x_phi's Wx into the x->PI / x->PO paths (12 CTAs)
__global__ void __launch_bounds__(256) kernelF4(
    const float* __restrict__ Wx, const float* __restrict__ bx) {
    const int t = blockIdx.x;
    if (t < 6) {                       // WxI = Wx @ Wihq (K=128), M=64 blocks
        const int c = t >> 1, mb = t & 1;
        small_gemmK(Wx + (size_t)c * F_ * HX_ + mb * 64 * HX_, HX_,
                    g_Wihq + (size_t)c * HX_ * H_, H_,
                    g_WxI + (size_t)c * F_ * H_ + mb * 64 * H_, 64, H_, HX_,
                    nullptr, 0);
    } else if (t < 9) {                // WxO = Wx @ Wxo (K=128)
        const int c = t - 6;
        small_gemmK(Wx + (size_t)c * F_ * HX_, HX_,
                    g_Wxo + (size_t)c * HX_ * F_, F_,
                    g_WxO + (size_t)c * F_ * F_, F_, F_, HX_, nullptr, 0);
    } else {                           // bihq2, bo3
        const int c = t - 9;
        small_gemmK(bx + c * HX_, HX_, g_Wihq + (size_t)c * HX_ * H_, H_,
                    g_bihq2 + c * H_, 1, H_, HX_, g_bihq + c * H_, 0);
        small_gemmK(bx + c * HX_, HX_, g_Wxo + (size_t)c * HX_ * F_, F_,
                    g_bo3 + c * F_, 1, F_, HX_, g_bo2 + c * F_, 0);
    }
}

// ===========================================================================
// Parallel GEMM machinery (kernels A and C)
// ===========================================================================
__device__ __forceinline__ void gemm64(const float* __restrict__ As,
                                       const float* __restrict__ Ws,
                                       int k0, float acc[8][8]) {
    const int tc = threadIdx.x & 15;
    const int tr = threadIdx.x >> 4;
    const float* ap = As + tr * 8 * 128 + k0;
    const float* bp = Ws + tc * 8;
#pragma unroll 4
    for (int k = 0; k < 64; ++k) {
        const float4 b0 = *reinterpret_cast<const float4*>(bp + k * 128);
        const float4 b1 = *reinterpret_cast<const float4*>(bp + k * 128 + 4);
        float a[8];
#pragma unroll
        for (int i = 0; i < 8; ++i) a[i] = ap[i * 128 + k];
        const float bv[8] = {b0.x, b0.y, b0.z, b0.w, b1.x, b1.y, b1.z, b1.w};
#pragma unroll
        for (int i = 0; i < 8; ++i)
#pragma unroll
            for (int j = 0; j < 8; ++j)
                acc[i][j] = fmaf(a[i], bv[j], acc[i][j]);
    }
}

// Load a 128x128 fp32 tile (row stride ld) into smem
__device__ __forceinline__ void load_tile(float* dst, const float* __restrict__ src,
                                          int ld) {
    for (int idx = threadIdx.x; idx < 128 * 32; idx += 256) {
        const int r = idx >> 5;
        const int c4 = idx & 31;
        reinterpret_cast<float4*>(dst)[(r << 5) + c4] =
            *reinterpret_cast<const float4*>(src + (size_t)r * ld + (c4 << 2));
    }
}

// Load a 64x128 fp32 slab (row stride ld) into smem
__device__ __forceinline__ void load_half(float* dst, const float* __restrict__ src,
                                          int ld) {
    for (int idx = threadIdx.x; idx < 64 * 32; idx += 256) {
        const int r = idx >> 5;
        const int c4 = idx & 31;
        reinterpret_cast<float4*>(dst)[(r << 5) + c4] =
            *reinterpret_cast<const float4*>(src + (size_t)r * ld + (c4 << 2));
    }
}

__device__ __forceinline__ void zero_acc(float acc[8][8]) {
#pragma unroll
    for (int i = 0; i < 8; ++i)
#pragma unroll
        for (int j = 0; j < 8; ++j) acc[i][j] = 0.f;
}

// full 128-deep GEMM as two 64-row slabs streamed through Ws
__device__ __forceinline__ void gemm128_slabs(const float* As, float* Ws,
                                              const float* __restrict__ W,
                                              int ldw, float acc[8][8]) {
#pragma unroll
    for (int h = 0; h < 2; ++h) {
        load_half(Ws, W + (size_t)(h * 64) * ldw, ldw);
        __syncthreads();
        gemm64(As, Ws, h * 64, acc);
        __syncthreads();
    }
}

// ---------------------------------------------------------------------------
// Kernel A: PO = x@WxO + bo3; PI = x@WxI + bihq2   (3 gemm units per tile)
// grid (4 btiles, T, C), 256 threads, 96KB dynamic smem
// ---------------------------------------------------------------------------
__global__ void __launch_bounds__(256, 2) kernelA(const float* __restrict__ x) {
    extern __shared__ float sm[];
    float* As = sm;                // 128x128
    float* Ws = sm + 128 * 128;    // 8192-float slab
    const int bt = blockIdx.x, t = blockIdx.y, c = blockIdx.z;
    const long rg0 = ((long)(c * T_ + t) * B_ + bt * 128);
    const int tc = threadIdx.x & 15, tr = threadIdx.x >> 4;

    load_tile(As, x + rg0 * F_, F_);   // ordered by sync inside gemm128_slabs

    float acc[8][8];

    // PO = x @ WxO + bo3
    zero_acc(acc);
    gemm128_slabs(As, Ws, g_WxO + (size_t)c * F_ * F_, F_, acc);
#pragma unroll
    for (int i = 0; i < 8; ++i)
#pragma unroll
        for (int j = 0; j < 8; ++j)
            g_PO[(rg0 + tr * 8 + i) * F_ + tc * 8 + j] =
                acc[i][j] + g_bo3[c * F_ + tc * 8 + j];

    // PI = x @ WxI + bihq2 (two 128-col halves)
#pragma unroll
    for (int half = 0; half < 2; ++half) {
        zero_acc(acc);
        gemm128_slabs(As, Ws, g_WxI + (size_t)c * F_ * H_ + half * 128, H_, acc);
#pragma unroll
        for (int i = 0; i < 8; ++i)
#pragma unroll
            for (int j = 0; j < 8; ++j) {
                const int n = half * 128 + tc * 8 + j;
                g_PI[(rg0 + tr * 8 + i) * H_ + n] =
                    acc[i][j] + g_bihq2[c * H_ + n];
            }
    }
}

// ===========================================================================
// Kernel B: the pure recurrence: h' = tanh(PI + h@Whh2). One GEMM per step.
// ===========================================================================
__device__ __forceinline__ float fast_tanh(float x) {
    // tanh(x) = 1 - 2/(exp(2x)+1); safe at +/-inf, abs err ~1e-7
    const float e = __expf(2.f * x);
    return 1.f - __fdividef(2.f, e + 1.f);
}

template <int K, int N>
__device__ __forceinline__ void mm4(const float* __restrict__ Wg,
                                    const float* __restrict__ a_s,
                                    float4 acc[RMAX_]) {
    constexpr int G = N / 4;      // thread groups (one per 4 columns)
    constexpr int P = 256 / G;    // k partitions
    constexpr int Ks = K / P;
    const int g = threadIdx.x % G;
    const int p = threadIdx.x / G;
    const float4* wp = reinterpret_cast<const float4*>(Wg) + (size_t)(p * Ks) * G + g;
    const float* ap = a_s + p * Ks;

    float4 w0 = wp[0 * G], w1 = wp[1 * G], w2 = wp[2 * G], w3 = wp[3 * G];
#pragma unroll 1
    for (int k = 0; k < Ks; k += 4) {
        float4 n0, n1, n2, n3;
        if (k + 4 < Ks) {
            n0 = wp[(k + 4) * G];
            n1 = wp[(k + 5) * G];
            n2 = wp[(k + 6) * G];
            n3 = wp[(k + 7) * G];
        }
#pragma unroll
        for (int r = 0; r < RMAX_; ++r) {
            const float4 a = *reinterpret_cast<const float4*>(ap + r * K + k);
            acc[r].x = fmaf(a.x, w0.x, acc[r].x);
            acc[r].y = fmaf(a.x, w0.y, acc[r].y);
            acc[r].z = fmaf(a.x, w0.z, acc[r].z);
            acc[r].w = fmaf(a.x, w0.w, acc[r].w);
            acc[r].x = fmaf(a.y, w1.x, acc[r].x);
            acc[r].y = fmaf(a.y, w1.y, acc[r].y);
            acc[r].z = fmaf(a.y, w1.z, acc[r].z);
            acc[r].w = fmaf(a.y, w1.w, acc[r].w);
            acc[r].x = fmaf(a.z, w2.x, acc[r].x);
            acc[r].y = fmaf(a.z, w2.y, acc[r].y);
            acc[r].z = fmaf(a.z, w2.z, acc[r].z);
            acc[r].w = fmaf(a.z, w2.w, acc[r].w);
            acc[r].x = fmaf(a.w, w3.x, acc[r].x);
            acc[r].y = fmaf(a.w, w3.y, acc[r].y);
            acc[r].z = fmaf(a.w, w3.z, acc[r].z);
            acc[r].w = fmaf(a.w, w3.w, acc[r].w);
        }
        w0 = n0; w1 = n1; w2 = n2; w3 = n3;
    }
}

template <int N>
__device__ __forceinline__ void store_scr(float* __restrict__ scr,
                                          const float4 acc[RMAX_]) {
    const int g = threadIdx.x % (N / 4);
    const int p = threadIdx.x / (N / 4);
#pragma unroll
    for (int r = 0; r < RMAX_; ++r)
        *reinterpret_cast<float4*>(scr + (size_t)(p * RMAX_ + r) * N + 4 * g) = acc[r];
}

__device__ __forceinline__ void zero4(float4 acc[RMAX_]) {
#pragma unroll
    for (int r = 0; r < RMAX_; ++r) acc[r] = make_float4(0.f, 0.f, 0.f, 0.f);
}

__global__ void __launch_bounds__(256, 2) kernelB(const float* __restrict__ h0) {
    // dynamic smem: hs[1536] | scr2[4*6*256=6144]  -> 30 KB
    extern __shared__ float smb[];
    float* hs   = smb;
    float* scr2 = smb + RMAX_ * H_;

    const int c = blockIdx.y;
    // overlapping coverage: 86 CTAs x 6 rows = 516 >= 512; duplicated rows
    // compute bit-identical values, duplicate global stores are benign.
    const int r0 = (blockIdx.x * (B_ - RMAX_)) / (NB_ - 1);
    const int tid = threadIdx.x;

    for (int idx = tid; idx < RMAX_ * H_; idx += 256)
        hs[idx] = h0[(size_t)(c * B_ + r0) * H_ + idx];
    __syncthreads();

    const float* Whh2 = g_Whh2 + (size_t)c * H_ * H_;
    float4 acc[RMAX_];

    long rg0 = (long)c * T_ * B_ + r0;
    for (int t = 0; t < T_; ++t, rg0 += B_) {
        // prefetch this step's PI into registers (overlaps with FMAs below)
        float pip[RMAX_];
#pragma unroll
        for (int j = 0; j < RMAX_; ++j)
            pip[j] = g_PI[rg0 * H_ + j * 256 + tid];

        zero4(acc);
        mm4<256, 256>(Whh2, hs, acc);      // h partials (P=4)
        store_scr<256>(scr2, acc);
        // store Hs[t] = h (pre-update) while partials land
        for (int idx = tid; idx < RMAX_ * H_ / 4; idx += 256)
            reinterpret_cast<float4*>(&g_Hs[rg0 * H_])[idx] =
                reinterpret_cast<const float4*>(hs)[idx];
        __syncthreads();

        // reduce 4 partials + PI -> tanh -> hs (1536 outputs)
#pragma unroll
        for (int j = 0; j < RMAX_; ++j) {
            const int idx = j * 256 + tid;
            const int r = idx >> 8;
            const int n = idx & 255;
            float s = pip[j];
#pragma unroll
            for (int p = 0; p < 4; ++p)
                s += scr2[(size_t)(p * RMAX_ + r) * 256 + n];
            hs[idx] = fast_tanh(s);
        }
        __syncthreads();
    }
}

// ---------------------------------------------------------------------------
// Kernel C: out = PO + Hs@Who2
// grid (4 btiles, T, C), 256 threads, 96KB dynamic smem
// ---------------------------------------------------------------------------
__global__ void __launch_bounds__(256, 2) kernelC(float* __restrict__ out) {
    extern __shared__ float sm[];
    float* As = sm;
    float* Ws = sm + 128 * 128;
    const int bt = blockIdx.x, t = blockIdx.y, c = blockIdx.z;
    const long rg0 = ((long)(c * T_ + t) * B_ + bt * 128);
    const int tc = threadIdx.x & 15, tr = threadIdx.x >> 4;

    float acc[8][8];
    zero_acc(acc);

    // h part: two 128-row slices of Who2 (K=256 total)
    load_tile(As, g_Hs + rg0 * H_, H_);
    gemm128_slabs(As, Ws, g_Who2 + (size_t)c * H_ * F_, F_, acc);
    load_tile(As, g_Hs + rg0 * H_ + 128, H_);
    gemm128_slabs(As, Ws, g_Who2 + (size_t)c * H_ * F_ + 128 * F_, F_, acc);

#pragma unroll
    for (int i = 0; i < 8; ++i)
#pragma unroll
        for (int j = 0; j < 8; ++j) {
            const long o = (rg0 + tr * 8 + i) * F_ + tc * 8 + j;
            out[o] = acc[i][j] + g_PO[o];
        }
}

// ---------------------------------------------------------------------------
extern "C" void kernel_launch(void* const* d_in, const int* in_sizes, int n_in,
                              void* d_out, int out_size) {
    (void)in_sizes; (void)n_in; (void)out_size;
    const float* x        = (const float*)d_in[0];
    const float* phi_x_W  = (const float*)d_in[1];
    const float* phi_x_b  = (const float*)d_in[2];
    const float* enc_W    = (const float*)d_in[3];
    const float* enc_b    = (const float*)d_in[4];
    const float* enc_mu_W = (const float*)d_in[5];
    const float* enc_mu_b = (const float*)d_in[6];
    const float* phi_z_W  = (const float*)d_in[7];
    const float* phi_z_b  = (const float*)d_in[8];
    const float* dec_W    = (const float*)d_in[9];
    const float* dec_b    = (const float*)d_in[10];
    const float* dec_mu_W = (const float*)d_in[11];
    const float* dec_mu_b = (const float*)d_in[12];
    const float* rnn_Wih  = (const float*)d_in[13];
    const float* rnn_Whh  = (const float*)d_in[14];
    const float* rnn_bih  = (const float*)d_in[15];
    const float* rnn_bhh  = (const float*)d_in[16];
    const float* h0       = (const float*)d_in[17];
    float* out = (float*)d_out;

    const size_t smemAC = (128 * 128 + 64 * 128) * sizeof(float);  // 96 KB
    const size_t smemB  = (RMAX_ * H_ + 4 * RMAX_ * 256) * sizeof(float); // 30 KB
    cudaFuncSetAttribute(kernelA, cudaFuncAttributeMaxDynamicSharedMemorySize,
                         (int)smemAC);
    cudaFuncSetAttribute(kernelB, cudaFuncAttributeMaxDynamicSharedMemorySize,
                         (int)smemB);
    cudaFuncSetAttribute(kernelC, cudaFuncAttributeMaxDynamicSharedMemorySize,
                         (int)smemAC);

    kernelF1<<<29, 256>>>(enc_W, enc_b, enc_mu_W, enc_mu_b, phi_z_W, phi_z_b,
                          dec_W, dec_b, rnn_Wih);
    kernelF2<<<39, 256>>>(dec_W, dec_mu_W, dec_mu_b, rnn_Whh, rnn_Wih,
                          rnn_bih, rnn_bhh);
    kernelF3<<<21, 256>>>();
    kernelF4<<<12, 256>>>(phi_x_W, phi_x_b);
    kernelA<<<dim3(4, T_, C_), 256, smemAC>>>(x);
    kernelB<<<dim3(NB_, C_), 256, smemB>>>(h0);
    kernelC<<<dim3(4, T_, C_), 256, smemAC>>>(out);
}

// round 10
// speedup vs baseline: 1.2870x; 1.2870x over previous
#include <cuda_runtime.h>
#include <math.h>

// Problem dims
#define C_   3
#define T_   100
#define B_   512
#define F_   128
#define HX_  128
#define HZ_  128
#define H_   256
#define EH_  128
#define L_   64

#define NB_   86   // CTAs per channel (86*6=516 >= 512; 258 CTAs, 1 wave @ 2/SM)
#define RMAX_ 6    // rows per CTA

// ---- big activations scratch ----
__device__ float g_PI[(size_t)C_ * T_ * B_ * H_];   // x@WxI + bihq2
__device__ float g_PO[(size_t)C_ * T_ * B_ * F_];   // x@WxO + bo3
__device__ float g_Hs[(size_t)C_ * T_ * B_ * H_];   // h at step input

// ---- folded weights (computed on-device each run; tiny) ----
__device__ float g_Weq[C_ * HX_ * L_];    // We_x @ Wqm              [128,64]/ch
__device__ float g_beq[C_ * L_];          // be@Wqm + bqm
__device__ float g_Wcomb[C_ * H_ * L_];   // We_h @ Wqm              [256,64]/ch
__device__ float g_Wihz[L_ * H_];         // Wzp @ Wih_z             [64,256]
__device__ float g_bihz[H_];              // bzp @ Wih_z
__device__ float g_Wdz[C_ * L_ * EH_];    // Wzp @ Wd_z              [64,128]/ch
__device__ float g_bdz[C_ * EH_];         // bzp@Wd_z + bd
__device__ float g_Wzo[C_ * L_ * F_];     // Wdz @ Wpm               [64,128]/ch
__device__ float g_Who[C_ * H_ * F_];     // Wd_h @ Wpm              [256,128]/ch
__device__ float g_bo[C_ * F_];           // bdz@Wpm + bpm
__device__ float g_Whh2[C_ * H_ * H_];    // Whh + Wcomb@Wihz        [256,256]/ch
__device__ float g_Wihq[C_ * HX_ * H_];   // Wih_x + Weq@Wihz        [128,256]/ch
__device__ float g_bihq[C_ * H_];         // bih+bhh+bihz + beq@Wihz
__device__ float g_Who2[C_ * H_ * F_];    // Who + Wcomb@Wzo         [256,128]/ch
__device__ float g_Wxo[C_ * HX_ * F_];    // Weq @ Wzo               [128,128]/ch
__device__ float g_bo2[C_ * F_];          // beq@Wzo + bo
__device__ float g_WxI[C_ * F_ * H_];     // Wx @ Wihq               [128,256]/ch
__device__ float g_bihq2[C_ * H_];        // bx@Wihq + bihq
__device__ float g_WxO[C_ * F_ * F_];     // Wx @ Wxo                [128,128]/ch
__device__ float g_bo3[C_ * F_];          // bx@Wxo + bo2

// ===========================================================================
// small GEMM for weight folding: out = A[M,K]@Bm[K,N] (+ addm)
// ILP version: each thread computes 4 output ROWS sharing every b-load.
// 4 independent FMA chains per thread; b-loads coalesced across the warp.
// ===========================================================================
__device__ __forceinline__ void small_gemmK(const float* __restrict__ A, int lda,
                                            const float* __restrict__ Bm, int ldb,
                                            float* __restrict__ out, int M, int N,
                                            int K, const float* __restrict__ addm,
                                            int ldam) {
    const int M4 = M >> 2;                 // groups of 4 rows
    for (int idx = threadIdx.x; idx < M4 * N; idx += 256) {
        const int mg = idx / N, n = idx % N;
        const int m = mg * 4;
        float s0 = addm ? addm[(size_t)(m + 0) * ldam + n] : 0.f;
        float s1 = addm ? addm[(size_t)(m + 1) * ldam + n] : 0.f;
        float s2 = addm ? addm[(size_t)(m + 2) * ldam + n] : 0.f;
        float s3 = addm ? addm[(size_t)(m + 3) * ldam + n] : 0.f;
        const float* a0 = A + (size_t)(m + 0) * lda;
        const float* a1 = A + (size_t)(m + 1) * lda;
        const float* a2 = A + (size_t)(m + 2) * lda;
        const float* a3 = A + (size_t)(m + 3) * lda;
        const float* b = Bm + n;
#pragma unroll 4
        for (int k = 0; k < K; ++k) {
            const float bv = b[(size_t)k * ldb];
            s0 = fmaf(a0[k], bv, s0);
            s1 = fmaf(a1[k], bv, s1);
            s2 = fmaf(a2[k], bv, s2);
            s3 = fmaf(a3[k], bv, s3);
        }
        out[(size_t)(m + 0) * N + n] = s0;
        out[(size_t)(m + 1) * N + n] = s1;
        out[(size_t)(m + 2) * N + n] = s2;
        out[(size_t)(m + 3) * N + n] = s3;
    }
    // remainder rows (e.g. M==1 bias tasks)
    const int mrem0 = M4 * 4;
    for (int idx = threadIdx.x; idx < (M - mrem0) * N; idx += 256) {
        const int m = mrem0 + idx / N, n = idx % N;
        float s = addm ? addm[(size_t)m * ldam + n] : 0.f;
        const float* a = A + (size_t)m * lda;
        const float* b = Bm + n;
#pragma unroll 4
        for (int k = 0; k < K; ++k) s = fmaf(a[k], b[(size_t)k * ldb], s);
        out[(size_t)m * N + n] = s;
    }
}

// fold stage 1: products of raw inputs (29 CTAs)
__global__ void __launch_bounds__(256) kernelF1(
    const float* __restrict__ We, const float* __restrict__ be,
    const float* __restrict__ Wqm, const float* __restrict__ bqm,
    const float* __restrict__ Wzp, const float* __restrict__ bzp,
    const float* __restrict__ Wd, const float* __restrict__ bd,
    const float* __restrict__ Wih) {
    const int t = blockIdx.x;
    if (t < 6) {                       // Weq blocks (M=64)
        const int c = t >> 1, rb = t & 1;
        small_gemmK(We + (size_t)c * 384 * EH_ + rb * 64 * EH_, EH_,
                    Wqm + (size_t)c * EH_ * L_, L_,
                    g_Weq + c * HX_ * L_ + rb * 64 * L_, 64, L_, EH_, nullptr, 0);
    } else if (t < 18) {               // Wcomb blocks
        const int u = t - 6, c = u >> 2, rb = u & 3;
        small_gemmK(We + (size_t)c * 384 * EH_ + (128 + rb * 64) * EH_, EH_,
                    Wqm + (size_t)c * EH_ * L_, L_,
                    g_Wcomb + c * H_ * L_ + rb * 64 * L_, 64, L_, EH_, nullptr, 0);
    } else if (t < 21) {               // Wdz = Wzp @ Wd_z
        const int c = t - 18;
        small_gemmK(Wzp, HZ_, Wd + (size_t)c * 384 * EH_, EH_,
                    g_Wdz + c * L_ * EH_, L_, EH_, HZ_, nullptr, 0);
    } else if (t == 21) {              // Wihz = Wzp @ Wih_z
        small_gemmK(Wzp, HZ_, Wih + 128 * H_, H_, g_Wihz, L_, H_, HZ_, nullptr, 0);
    } else if (t < 25) {               // beq = be@Wqm + bqm
        const int c = t - 22;
        small_gemmK(be + c * EH_, EH_, Wqm + (size_t)c * EH_ * L_, L_,
                    g_beq + c * L_, 1, L_, EH_, bqm + c * L_, 0);
    } else if (t < 28) {               // bdz = bzp@Wd_z + bd
        const int c = t - 25;
        small_gemmK(bzp, HZ_, Wd + (size_t)c * 384 * EH_, EH_,
                    g_bdz + c * EH_, 1, EH_, HZ_, bd + c * EH_, 0);
    } else {                           // bihz = bzp@Wih_z
        small_gemmK(bzp, HZ_, Wih + 128 * H_, H_, g_bihz, 1, H_, HZ_, nullptr, 0);
    }
}

// fold stage 2: products involving fold-1 outputs (39 CTAs)
__global__ void __launch_bounds__(256) kernelF2(
    const float* __restrict__ Wd, const float* __restrict__ Wpm,
    const float* __restrict__ bpm, const float* __restrict__ Whh,
    const float* __restrict__ Wih, const float* __restrict__ bih,
    const float* __restrict__ bhh) {
    const int t = blockIdx.x;
    if (t < 3) {                       // Wzo = Wdz @ Wpm
        const int c = t;
        small_gemmK(g_Wdz + c * L_ * EH_, EH_, Wpm + (size_t)c * EH_ * F_, F_,
                    g_Wzo + c * L_ * F_, L_, F_, EH_, nullptr, 0);
    } else if (t < 15) {               // Who = Wd_h @ Wpm
        const int u = t - 3, c = u >> 2, rb = u & 3;
        small_gemmK(Wd + (size_t)c * 384 * EH_ + (128 + rb * 64) * EH_, EH_,
                    Wpm + (size_t)c * EH_ * F_, F_,
                    g_Who + c * H_ * F_ + rb * 64 * F_, 64, F_, EH_, nullptr, 0);
    } else if (t < 18) {               // bo = bdz@Wpm + bpm
        const int c = t - 15;
        small_gemmK(g_bdz + c * EH_, EH_, Wpm + (size_t)c * EH_ * F_, F_,
                    g_bo + c * F_, 1, F_, EH_, bpm + c * F_, 0);
    } else if (t < 30) {               // Whh2 = Whh + Wcomb @ Wihz (K=64)
        const int u = t - 18, c = u >> 2, mb = u & 3;
        small_gemmK(g_Wcomb + c * H_ * L_ + mb * 64 * L_, L_,
                    g_Wihz, H_,
                    g_Whh2 + (size_t)c * H_ * H_ + mb * 64 * H_, 64, H_, L_,
                    Whh + (size_t)mb * 64 * H_, H_);
    } else if (t < 36) {               // Wihq = Wih_x + Weq @ Wihz (K=64)
        const int u = t - 30, c = u >> 1, mb = u & 1;
        small_gemmK(g_Weq + c * HX_ * L_ + mb * 64 * L_, L_,
                    g_Wihz, H_,
                    g_Wihq + (size_t)c * HX_ * H_ + mb * 64 * H_, 64, H_, L_,
                    Wih + (size_t)mb * 64 * H_, H_);
    } else {                           // bihq = bih+bhh+bihz + beq@Wihz
        const int c = t - 36;
        for (int n = threadIdx.x; n < H_; n += 256) {
            float s = bih[n] + bhh[n] + g_bihz[n];
            for (int l = 0; l < L_; ++l)
                s = fmaf(g_beq[c * L_ + l], g_Wihz[l * H_ + n], s);
            g_bihq[c * H_ + n] = s;
        }
    }
}

// fold stage 3: output-path folds (21 CTAs)
__global__ void __launch_bounds__(256) kernelF3() {
    const int t = blockIdx.x;
    if (t < 12) {                      // Who2 = Who + Wcomb @ Wzo (K=64)
        const int c = t >> 2, mb = t & 3;
        small_gemmK(g_Wcomb + c * H_ * L_ + mb * 64 * L_, L_,
                    g_Wzo + c * L_ * F_, F_,
                    g_Who2 + c * H_ * F_ + mb * 64 * F_, 64, F_, L_,
                    g_Who + c * H_ * F_ + mb * 64 * F_, F_);
    } else if (t < 18) {               // Wxo = Weq @ Wzo (K=64)
        const int u = t - 12, c = u >> 1, mb = u & 1;
        small_gemmK(g_Weq + c * HX_ * L_ + mb * 64 * L_, L_,
                    g_Wzo + c * L_ * F_, F_,
                    g_Wxo + c * HX_ * F_ + mb * 64 * F_, 64, F_, L_, nullptr, 0);
    } else {                           // bo2 = beq@Wzo + bo
        const int c = t - 18;
        small_gemmK(g_beq + c * L_, L_, g_Wzo + c * L_ * F_, F_,
                    g_bo2 + c * F_, 1, F_, L_, g_bo + c * F_, 0);
    }
}

// fold stage 4: fold x_phi's Wx into the x->PI / x->PO paths (12 CTAs)
__global__ void __launch_bounds__(256) kernelF4(
    const float* __restrict__ Wx, const float* __restrict__ bx) {
    const int t = blockIdx.x;
    if (t < 6) {                       // WxI = Wx @ Wihq (K=128), M=64 blocks
        const int c = t >> 1, mb = t & 1;
        small_gemmK(Wx + (size_t)c * F_ * HX_ + mb * 64 * HX_, HX_,
                    g_Wihq + (size_t)c * HX_ * H_, H_,
                    g_WxI + (size_t)c * F_ * H_ + mb * 64 * H_, 64, H_, HX_,
                    nullptr, 0);
    } else if (t < 9) {                // WxO = Wx @ Wxo (K=128)
        const int c = t - 6;
        small_gemmK(Wx + (size_t)c * F_ * HX_, HX_,
                    g_Wxo + (size_t)c * HX_ * F_, F_,
                    g_WxO + (size_t)c * F_ * F_, F_, F_, HX_, nullptr, 0);
    } else {                           // bihq2, bo3
        const int c = t - 9;
        small_gemmK(bx + c * HX_, HX_, g_Wihq + (size_t)c * HX_ * H_, H_,
                    g_bihq2 + c * H_, 1, H_, HX_, g_bihq + c * H_, 0);
        small_gemmK(bx + c * HX_, HX_, g_Wxo + (size_t)c * HX_ * F_, F_,
                    g_bo3 + c * F_, 1, F_, HX_, g_bo2 + c * F_, 0);
    }
}

// ===========================================================================
// Parallel GEMM machinery (kernels A and C)
// ===========================================================================
__device__ __forceinline__ void gemm64(const float* __restrict__ As,
                                       const float* __restrict__ Ws,
                                       int k0, float acc[8][8]) {
    const int tc = threadIdx.x & 15;
    const int tr = threadIdx.x >> 4;
    const float* ap = As + tr * 8 * 128 + k0;
    const float* bp = Ws + tc * 8;
#pragma unroll 4
    for (int k = 0; k < 64; ++k) {
        const float4 b0 = *reinterpret_cast<const float4*>(bp + k * 128);
        const float4 b1 = *reinterpret_cast<const float4*>(bp + k * 128 + 4);
        float a[8];
#pragma unroll
        for (int i = 0; i < 8; ++i) a[i] = ap[i * 128 + k];
        const float bv[8] = {b0.x, b0.y, b0.z, b0.w, b1.x, b1.y, b1.z, b1.w};
#pragma unroll
        for (int i = 0; i < 8; ++i)
#pragma unroll
            for (int j = 0; j < 8; ++j)
                acc[i][j] = fmaf(a[i], bv[j], acc[i][j]);
    }
}

// Load a 128x128 fp32 tile (row stride ld) into smem
__device__ __forceinline__ void load_tile(float* dst, const float* __restrict__ src,
                                          int ld) {
    for (int idx = threadIdx.x; idx < 128 * 32; idx += 256) {
        const int r = idx >> 5;
        const int c4 = idx & 31;
        reinterpret_cast<float4*>(dst)[(r << 5) + c4] =
            *reinterpret_cast<const float4*>(src + (size_t)r * ld + (c4 << 2));
    }
}

// Load a 64x128 fp32 slab (row stride ld) into smem
__device__ __forceinline__ void load_half(float* dst, const float* __restrict__ src,
                                          int ld) {
    for (int idx = threadIdx.x; idx < 64 * 32; idx += 256) {
        const int r = idx >> 5;
        const int c4 = idx & 31;
        reinterpret_cast<float4*>(dst)[(r << 5) + c4] =
            *reinterpret_cast<const float4*>(src + (size_t)r * ld + (c4 << 2));
    }
}

__device__ __forceinline__ void zero_acc(float acc[8][8]) {
#pragma unroll
    for (int i = 0; i < 8; ++i)
#pragma unroll
        for (int j = 0; j < 8; ++j) acc[i][j] = 0.f;
}

// full 128-deep GEMM as two 64-row slabs streamed through Ws
__device__ __forceinline__ void gemm128_slabs(const float* As, float* Ws,
                                              const float* __restrict__ W,
                                              int ldw, float acc[8][8]) {
#pragma unroll
    for (int h = 0; h < 2; ++h) {
        load_half(Ws, W + (size_t)(h * 64) * ldw, ldw);
        __syncthreads();
        gemm64(As, Ws, h * 64, acc);
        __syncthreads();
    }
}

// ---------------------------------------------------------------------------
// Kernel A: PO = x@WxO + bo3; PI = x@WxI + bihq2   (3 gemm units per tile)
// grid (4 btiles, T, C), 256 threads, 96KB dynamic smem
// ---------------------------------------------------------------------------
__global__ void __launch_bounds__(256, 2) kernelA(const float* __restrict__ x) {
    extern __shared__ float sm[];
    float* As = sm;                // 128x128
    float* Ws = sm + 128 * 128;    // 8192-float slab
    const int bt = blockIdx.x, t = blockIdx.y, c = blockIdx.z;
    const long rg0 = ((long)(c * T_ + t) * B_ + bt * 128);
    const int tc = threadIdx.x & 15, tr = threadIdx.x >> 4;

    load_tile(As, x + rg0 * F_, F_);   // ordered by sync inside gemm128_slabs

    float acc[8][8];

    // PO = x @ WxO + bo3
    zero_acc(acc);
    gemm128_slabs(As, Ws, g_WxO + (size_t)c * F_ * F_, F_, acc);
#pragma unroll
    for (int i = 0; i < 8; ++i)
#pragma unroll
        for (int j = 0; j < 8; ++j)
            g_PO[(rg0 + tr * 8 + i) * F_ + tc * 8 + j] =
                acc[i][j] + g_bo3[c * F_ + tc * 8 + j];

    // PI = x @ WxI + bihq2 (two 128-col halves)
#pragma unroll
    for (int half = 0; half < 2; ++half) {
        zero_acc(acc);
        gemm128_slabs(As, Ws, g_WxI + (size_t)c * F_ * H_ + half * 128, H_, acc);
#pragma unroll
        for (int i = 0; i < 8; ++i)
#pragma unroll
            for (int j = 0; j < 8; ++j) {
                const int n = half * 128 + tc * 8 + j;
                g_PI[(rg0 + tr * 8 + i) * H_ + n] =
                    acc[i][j] + g_bihq2[c * H_ + n];
            }
    }
}

// ===========================================================================
// Kernel B: the pure recurrence: h' = tanh(PI + h@Whh2). One GEMM per step.
// ===========================================================================
__device__ __forceinline__ float fast_tanh(float x) {
    // tanh(x) = 1 - 2/(exp(2x)+1); safe at +/-inf, abs err ~1e-7
    const float e = __expf(2.f * x);
    return 1.f - __fdividef(2.f, e + 1.f);
}

template <int K, int N>
__device__ __forceinline__ void mm4(const float* __restrict__ Wg,
                                    const float* __restrict__ a_s,
                                    float4 acc[RMAX_]) {
    constexpr int G = N / 4;      // thread groups (one per 4 columns)
    constexpr int P = 256 / G;    // k partitions
    constexpr int Ks = K / P;
    const int g = threadIdx.x % G;
    const int p = threadIdx.x / G;
    const float4* wp = reinterpret_cast<const float4*>(Wg) + (size_t)(p * Ks) * G + g;
    const float* ap = a_s + p * Ks;

    float4 w0 = wp[0 * G], w1 = wp[1 * G], w2 = wp[2 * G], w3 = wp[3 * G];
#pragma unroll 1
    for (int k = 0; k < Ks; k += 4) {
        float4 n0, n1, n2, n3;
        if (k + 4 < Ks) {
            n0 = wp[(k + 4) * G];
            n1 = wp[(k + 5) * G];
            n2 = wp[(k + 6) * G];
            n3 = wp[(k + 7) * G];
        }
#pragma unroll
        for (int r = 0; r < RMAX_; ++r) {
            const float4 a = *reinterpret_cast<const float4*>(ap + r * K + k);
            acc[r].x = fmaf(a.x, w0.x, acc[r].x);
            acc[r].y = fmaf(a.x, w0.y, acc[r].y);
            acc[r].z = fmaf(a.x, w0.z, acc[r].z);
            acc[r].w = fmaf(a.x, w0.w, acc[r].w);
            acc[r].x = fmaf(a.y, w1.x, acc[r].x);
            acc[r].y = fmaf(a.y, w1.y, acc[r].y);
            acc[r].z = fmaf(a.y, w1.z, acc[r].z);
            acc[r].w = fmaf(a.y, w1.w, acc[r].w);
            acc[r].x = fmaf(a.z, w2.x, acc[r].x);
            acc[r].y = fmaf(a.z, w2.y, acc[r].y);
            acc[r].z = fmaf(a.z, w2.z, acc[r].z);
            acc[r].w = fmaf(a.z, w2.w, acc[r].w);
            acc[r].x = fmaf(a.w, w3.x, acc[r].x);
            acc[r].y = fmaf(a.w, w3.y, acc[r].y);
            acc[r].z = fmaf(a.w, w3.z, acc[r].z);
            acc[r].w = fmaf(a.w, w3.w, acc[r].w);
        }
        w0 = n0; w1 = n1; w2 = n2; w3 = n3;
    }
}

template <int N>
__device__ __forceinline__ void store_scr(float* __restrict__ scr,
                                          const float4 acc[RMAX_]) {
    const int g = threadIdx.x % (N / 4);
    const int p = threadIdx.x / (N / 4);
#pragma unroll
    for (int r = 0; r < RMAX_; ++r)
        *reinterpret_cast<float4*>(scr + (size_t)(p * RMAX_ + r) * N + 4 * g) = acc[r];
}

__device__ __forceinline__ void zero4(float4 acc[RMAX_]) {
#pragma unroll
    for (int r = 0; r < RMAX_; ++r) acc[r] = make_float4(0.f, 0.f, 0.f, 0.f);
}

__global__ void __launch_bounds__(256, 2) kernelB(const float* __restrict__ h0) {
    // dynamic smem: hs[1536] | scr2[4*6*256=6144]  -> 30 KB
    extern __shared__ float smb[];
    float* hs   = smb;
    float* scr2 = smb + RMAX_ * H_;

    const int c = blockIdx.y;
    // overlapping coverage: 86 CTAs x 6 rows = 516 >= 512; duplicated rows
    // compute bit-identical values, duplicate global stores are benign.
    const int r0 = (blockIdx.x * (B_ - RMAX_)) / (NB_ - 1);
    const int tid = threadIdx.x;

    for (int idx = tid; idx < RMAX_ * H_; idx += 256)
        hs[idx] = h0[(size_t)(c * B_ + r0) * H_ + idx];
    __syncthreads();

    const float* Whh2 = g_Whh2 + (size_t)c * H_ * H_;
    float4 acc[RMAX_];

    long rg0 = (long)c * T_ * B_ + r0;
    for (int t = 0; t < T_; ++t, rg0 += B_) {
        // prefetch this step's PI into registers (overlaps with FMAs below)
        float pip[RMAX_];
#pragma unroll
        for (int j = 0; j < RMAX_; ++j)
            pip[j] = g_PI[rg0 * H_ + j * 256 + tid];

        zero4(acc);
        mm4<256, 256>(Whh2, hs, acc);      // h partials (P=4)
        store_scr<256>(scr2, acc);
        // store Hs[t] = h (pre-update) while partials land
        for (int idx = tid; idx < RMAX_ * H_ / 4; idx += 256)
            reinterpret_cast<float4*>(&g_Hs[rg0 * H_])[idx] =
                reinterpret_cast<const float4*>(hs)[idx];
        __syncthreads();

        // reduce 4 partials + PI -> tanh -> hs (1536 outputs)
#pragma unroll
        for (int j = 0; j < RMAX_; ++j) {
            const int idx = j * 256 + tid;
            const int r = idx >> 8;
            const int n = idx & 255;
            float s = pip[j];
#pragma unroll
            for (int p = 0; p < 4; ++p)
                s += scr2[(size_t)(p * RMAX_ + r) * 256 + n];
            hs[idx] = fast_tanh(s);
        }
        __syncthreads();
    }
}

// ---------------------------------------------------------------------------
// Kernel C: out = PO + Hs@Who2
// grid (4 btiles, T, C), 256 threads, 96KB dynamic smem
// ---------------------------------------------------------------------------
__global__ void __launch_bounds__(256, 2) kernelC(float* __restrict__ out) {
    extern __shared__ float sm[];
    float* As = sm;
    float* Ws = sm + 128 * 128;
    const int bt = blockIdx.x, t = blockIdx.y, c = blockIdx.z;
    const long rg0 = ((long)(c * T_ + t) * B_ + bt * 128);
    const int tc = threadIdx.x & 15, tr = threadIdx.x >> 4;

    float acc[8][8];
    zero_acc(acc);

    // h part: two 128-row slices of Who2 (K=256 total)
    load_tile(As, g_Hs + rg0 * H_, H_);
    gemm128_slabs(As, Ws, g_Who2 + (size_t)c * H_ * F_, F_, acc);
    load_tile(As, g_Hs + rg0 * H_ + 128, H_);
    gemm128_slabs(As, Ws, g_Who2 + (size_t)c * H_ * F_ + 128 * F_, F_, acc);

#pragma unroll
    for (int i = 0; i < 8; ++i)
#pragma unroll
        for (int j = 0; j < 8; ++j) {
            const long o = (rg0 + tr * 8 + i) * F_ + tc * 8 + j;
            out[o] = acc[i][j] + g_PO[o];
        }
}

// ---------------------------------------------------------------------------
extern "C" void kernel_launch(void* const* d_in, const int* in_sizes, int n_in,
                              void* d_out, int out_size) {
    (void)in_sizes; (void)n_in; (void)out_size;
    const float* x        = (const float*)d_in[0];
    const float* phi_x_W  = (const float*)d_in[1];
    const float* phi_x_b  = (const float*)d_in[2];
    const float* enc_W    = (const float*)d_in[3];
    const float* enc_b    = (const float*)d_in[4];
    const float* enc_mu_W = (const float*)d_in[5];
    const float* enc_mu_b = (const float*)d_in[6];
    const float* phi_z_W  = (const float*)d_in[7];
    const float* phi_z_b  = (const float*)d_in[8];
    const float* dec_W    = (const float*)d_in[9];
    const float* dec_b    = (const float*)d_in[10];
    const float* dec_mu_W = (const float*)d_in[11];
    const float* dec_mu_b = (const float*)d_in[12];
    const float* rnn_Wih  = (const float*)d_in[13];
    const float* rnn_Whh  = (const float*)d_in[14];
    const float* rnn_bih  = (const float*)d_in[15];
    const float* rnn_bhh  = (const float*)d_in[16];
    const float* h0       = (const float*)d_in[17];
    float* out = (float*)d_out;

    const size_t smemAC = (128 * 128 + 64 * 128) * sizeof(float);  // 96 KB
    const size_t smemB  = (RMAX_ * H_ + 4 * RMAX_ * 256) * sizeof(float); // 30 KB
    cudaFuncSetAttribute(kernelA, cudaFuncAttributeMaxDynamicSharedMemorySize,
                         (int)smemAC);
    cudaFuncSetAttribute(kernelB, cudaFuncAttributeMaxDynamicSharedMemorySize,
                         (int)smemB);
    cudaFuncSetAttribute(kernelC, cudaFuncAttributeMaxDynamicSharedMemorySize,
                         (int)smemAC);

    kernelF1<<<29, 256>>>(enc_W, enc_b, enc_mu_W, enc_mu_b, phi_z_W, phi_z_b,
                          dec_W, dec_b, rnn_Wih);
    kernelF2<<<39, 256>>>(dec_W, dec_mu_W, dec_mu_b, rnn_Whh, rnn_Wih,
                          rnn_bih, rnn_bhh);
    kernelF3<<<21, 256>>>();
    kernelF4<<<12, 256>>>(phi_x_W, phi_x_b);
    kernelA<<<dim3(4, T_, C_), 256, smemAC>>>(x);
    kernelB<<<dim3(NB_, C_), 256, smemB>>>(h0);
    kernelC<<<dim3(4, T_, C_), 256, smemAC>>>(out);
}

// round 11
// speedup vs baseline: 1.3900x; 1.0800x over previous
#include <cuda_runtime.h>
#include <math.h>

// Problem dims
#define C_   3
#define T_   100
#define B_   512
#define F_   128
#define HX_  128
#define HZ_  128
#define H_   256
#define EH_  128
#define L_   64

#define NB_   86   // CTAs per channel (86*6=516 >= 512; 258 CTAs, 1 wave @ 2/SM)
#define RMAX_ 6    // rows per CTA

// ---- big activations scratch ----
__device__ float g_PI[(size_t)C_ * T_ * B_ * H_];   // x@WxI + bihq2
__device__ float g_PO[(size_t)C_ * T_ * B_ * F_];   // x@WxO + bo3
__device__ float g_Hs[(size_t)C_ * T_ * B_ * H_];   // h at step input

// ---- folded weights (computed on-device each run; tiny) ----
__device__ float g_Weq[C_ * HX_ * L_];    // We_x @ Wqm              [128,64]/ch
__device__ float g_beq[C_ * L_];          // be@Wqm + bqm
__device__ float g_Wcomb[C_ * H_ * L_];   // We_h @ Wqm              [256,64]/ch
__device__ float g_Wihz[L_ * H_];         // Wzp @ Wih_z             [64,256]
__device__ float g_bihz[H_];              // bzp @ Wih_z
__device__ float g_Wdz[C_ * L_ * EH_];    // Wzp @ Wd_z              [64,128]/ch
__device__ float g_bdz[C_ * EH_];         // bzp@Wd_z + bd
__device__ float g_Wzo[C_ * L_ * F_];     // Wdz @ Wpm               [64,128]/ch
__device__ float g_Who[C_ * H_ * F_];     // Wd_h @ Wpm              [256,128]/ch
__device__ float g_bo[C_ * F_];           // bdz@Wpm + bpm
__device__ float g_Whh2[C_ * H_ * H_];    // Whh + Wcomb@Wihz        [256,256]/ch
__device__ float g_Wihq[C_ * HX_ * H_];   // Wih_x + Weq@Wihz        [128,256]/ch
__device__ float g_bihq[C_ * H_];         // bih+bhh+bihz + beq@Wihz
__device__ float g_Who2[C_ * H_ * F_];    // Who + Wcomb@Wzo         [256,128]/ch
__device__ float g_Wxo[C_ * HX_ * F_];    // Weq @ Wzo               [128,128]/ch
__device__ float g_bo2[C_ * F_];          // beq@Wzo + bo
__device__ float g_WxI[C_ * F_ * H_];     // Wx @ Wihq               [128,256]/ch
__device__ float g_bihq2[C_ * H_];        // bx@Wihq + bihq
__device__ float g_WxO[C_ * F_ * F_];     // Wx @ Wxo                [128,128]/ch
__device__ float g_bo3[C_ * F_];          // bx@Wxo + bo2

// ===========================================================================
// small GEMM for weight folding: out = A[M,K]@Bm[K,N] (+ addm)
// 4x4 register tile per thread: float4 b-loads, 16 FMA per k, 4 indep chains.
// N must be a multiple of 4 (all callers: 64/128/256). M%4 handled by scalar
// remainder (covers M==1 bias tasks).
// ===========================================================================
__device__ __forceinline__ void small_gemmK(const float* __restrict__ A, int lda,
                                            const float* __restrict__ Bm, int ldb,
                                            float* __restrict__ out, int M, int N,
                                            int K, const float* __restrict__ addm,
                                            int ldam) {
    const int M4 = M >> 2;
    const int Nq = N >> 2;
    for (int idx = threadIdx.x; idx < M4 * Nq; idx += 256) {
        const int mg = idx / Nq, ng = idx % Nq;
        const int m = mg * 4, n = ng * 4;
        float4 s0, s1, s2, s3;
        if (addm) {
            s0 = *reinterpret_cast<const float4*>(addm + (size_t)(m + 0) * ldam + n);
            s1 = *reinterpret_cast<const float4*>(addm + (size_t)(m + 1) * ldam + n);
            s2 = *reinterpret_cast<const float4*>(addm + (size_t)(m + 2) * ldam + n);
            s3 = *reinterpret_cast<const float4*>(addm + (size_t)(m + 3) * ldam + n);
        } else {
            s0 = s1 = s2 = s3 = make_float4(0.f, 0.f, 0.f, 0.f);
        }
        const float* a0 = A + (size_t)(m + 0) * lda;
        const float* a1 = A + (size_t)(m + 1) * lda;
        const float* a2 = A + (size_t)(m + 2) * lda;
        const float* a3 = A + (size_t)(m + 3) * lda;
        const float* b = Bm + n;
#pragma unroll 4
        for (int k = 0; k < K; ++k) {
            const float4 bv = *reinterpret_cast<const float4*>(b + (size_t)k * ldb);
            const float v0 = a0[k], v1 = a1[k], v2 = a2[k], v3 = a3[k];
            s0.x = fmaf(v0, bv.x, s0.x); s0.y = fmaf(v0, bv.y, s0.y);
            s0.z = fmaf(v0, bv.z, s0.z); s0.w = fmaf(v0, bv.w, s0.w);
            s1.x = fmaf(v1, bv.x, s1.x); s1.y = fmaf(v1, bv.y, s1.y);
            s1.z = fmaf(v1, bv.z, s1.z); s1.w = fmaf(v1, bv.w, s1.w);
            s2.x = fmaf(v2, bv.x, s2.x); s2.y = fmaf(v2, bv.y, s2.y);
            s2.z = fmaf(v2, bv.z, s2.z); s2.w = fmaf(v2, bv.w, s2.w);
            s3.x = fmaf(v3, bv.x, s3.x); s3.y = fmaf(v3, bv.y, s3.y);
            s3.z = fmaf(v3, bv.z, s3.z); s3.w = fmaf(v3, bv.w, s3.w);
        }
        *reinterpret_cast<float4*>(out + (size_t)(m + 0) * N + n) = s0;
        *reinterpret_cast<float4*>(out + (size_t)(m + 1) * N + n) = s1;
        *reinterpret_cast<float4*>(out + (size_t)(m + 2) * N + n) = s2;
        *reinterpret_cast<float4*>(out + (size_t)(m + 3) * N + n) = s3;
    }
    // remainder rows (e.g. M==1 bias tasks)
    const int mrem0 = M4 * 4;
    for (int idx = threadIdx.x; idx < (M - mrem0) * N; idx += 256) {
        const int m = mrem0 + idx / N, n = idx % N;
        float s = addm ? addm[(size_t)m * ldam + n] : 0.f;
        const float* a = A + (size_t)m * lda;
        const float* b = Bm + n;
#pragma unroll 4
        for (int k = 0; k < K; ++k) s = fmaf(a[k], b[(size_t)k * ldb], s);
        out[(size_t)m * N + n] = s;
    }
}

// fold stage 1: products of raw inputs (29 CTAs)
__global__ void __launch_bounds__(256) kernelF1(
    const float* __restrict__ We, const float* __restrict__ be,
    const float* __restrict__ Wqm, const float* __restrict__ bqm,
    const float* __restrict__ Wzp, const float* __restrict__ bzp,
    const float* __restrict__ Wd, const float* __restrict__ bd,
    const float* __restrict__ Wih) {
    const int t = blockIdx.x;
    if (t < 6) {                       // Weq blocks (M=64)
        const int c = t >> 1, rb = t & 1;
        small_gemmK(We + (size_t)c * 384 * EH_ + rb * 64 * EH_, EH_,
                    Wqm + (size_t)c * EH_ * L_, L_,
                    g_Weq + c * HX_ * L_ + rb * 64 * L_, 64, L_, EH_, nullptr, 0);
    } else if (t < 18) {               // Wcomb blocks
        const int u = t - 6, c = u >> 2, rb = u & 3;
        small_gemmK(We + (size_t)c * 384 * EH_ + (128 + rb * 64) * EH_, EH_,
                    Wqm + (size_t)c * EH_ * L_, L_,
                    g_Wcomb + c * H_ * L_ + rb * 64 * L_, 64, L_, EH_, nullptr, 0);
    } else if (t < 21) {               // Wdz = Wzp @ Wd_z
        const int c = t - 18;
        small_gemmK(Wzp, HZ_, Wd + (size_t)c * 384 * EH_, EH_,
                    g_Wdz + c * L_ * EH_, L_, EH_, HZ_, nullptr, 0);
    } else if (t == 21) {              // Wihz = Wzp @ Wih_z
        small_gemmK(Wzp, HZ_, Wih + 128 * H_, H_, g_Wihz, L_, H_, HZ_, nullptr, 0);
    } else if (t < 25) {               // beq = be@Wqm + bqm
        const int c = t - 22;
        small_gemmK(be + c * EH_, EH_, Wqm + (size_t)c * EH_ * L_, L_,
                    g_beq + c * L_, 1, L_, EH_, bqm + c * L_, 0);
    } else if (t < 28) {               // bdz = bzp@Wd_z + bd
        const int c = t - 25;
        small_gemmK(bzp, HZ_, Wd + (size_t)c * 384 * EH_, EH_,
                    g_bdz + c * EH_, 1, EH_, HZ_, bd + c * EH_, 0);
    } else {                           // bihz = bzp@Wih_z
        small_gemmK(bzp, HZ_, Wih + 128 * H_, H_, g_bihz, 1, H_, HZ_, nullptr, 0);
    }
}

// fold stage 2: products involving fold-1 outputs (39 CTAs)
__global__ void __launch_bounds__(256) kernelF2(
    const float* __restrict__ Wd, const float* __restrict__ Wpm,
    const float* __restrict__ bpm, const float* __restrict__ Whh,
    const float* __restrict__ Wih, const float* __restrict__ bih,
    const float* __restrict__ bhh) {
    const int t = blockIdx.x;
    if (t < 3) {                       // Wzo = Wdz @ Wpm
        const int c = t;
        small_gemmK(g_Wdz + c * L_ * EH_, EH_, Wpm + (size_t)c * EH_ * F_, F_,
                    g_Wzo + c * L_ * F_, L_, F_, EH_, nullptr, 0);
    } else if (t < 15) {               // Who = Wd_h @ Wpm
        const int u = t - 3, c = u >> 2, rb = u & 3;
        small_gemmK(Wd + (size_t)c * 384 * EH_ + (128 + rb * 64) * EH_, EH_,
                    Wpm + (size_t)c * EH_ * F_, F_,
                    g_Who + c * H_ * F_ + rb * 64 * F_, 64, F_, EH_, nullptr, 0);
    } else if (t < 18) {               // bo = bdz@Wpm + bpm
        const int c = t - 15;
        small_gemmK(g_bdz + c * EH_, EH_, Wpm + (size_t)c * EH_ * F_, F_,
                    g_bo + c * F_, 1, F_, EH_, bpm + c * F_, 0);
    } else if (t < 30) {               // Whh2 = Whh + Wcomb @ Wihz (K=64)
        const int u = t - 18, c = u >> 2, mb = u & 3;
        small_gemmK(g_Wcomb + c * H_ * L_ + mb * 64 * L_, L_,
                    g_Wihz, H_,
                    g_Whh2 + (size_t)c * H_ * H_ + mb * 64 * H_, 64, H_, L_,
                    Whh + (size_t)mb * 64 * H_, H_);
    } else if (t < 36) {               // Wihq = Wih_x + Weq @ Wihz (K=64)
        const int u = t - 30, c = u >> 1, mb = u & 1;
        small_gemmK(g_Weq + c * HX_ * L_ + mb * 64 * L_, L_,
                    g_Wihz, H_,
                    g_Wihq + (size_t)c * HX_ * H_ + mb * 64 * H_, 64, H_, L_,
                    Wih + (size_t)mb * 64 * H_, H_);
    } else {                           // bihq = bih+bhh+bihz + beq@Wihz
        const int c = t - 36;
        for (int n = threadIdx.x; n < H_; n += 256) {
            float s = bih[n] + bhh[n] + g_bihz[n];
            for (int l = 0; l < L_; ++l)
                s = fmaf(g_beq[c * L_ + l], g_Wihz[l * H_ + n], s);
            g_bihq[c * H_ + n] = s;
        }
    }
}

// fold stage 3: output-path folds (21 CTAs)
__global__ void __launch_bounds__(256) kernelF3() {
    const int t = blockIdx.x;
    if (t < 12) {                      // Who2 = Who + Wcomb @ Wzo (K=64)
        const int c = t >> 2, mb = t & 3;
        small_gemmK(g_Wcomb + c * H_ * L_ + mb * 64 * L_, L_,
                    g_Wzo + c * L_ * F_, F_,
                    g_Who2 + c * H_ * F_ + mb * 64 * F_, 64, F_, L_,
                    g_Who + c * H_ * F_ + mb * 64 * F_, F_);
    } else if (t < 18) {               // Wxo = Weq @ Wzo (K=64)
        const int u = t - 12, c = u >> 1, mb = u & 1;
        small_gemmK(g_Weq + c * HX_ * L_ + mb * 64 * L_, L_,
                    g_Wzo + c * L_ * F_, F_,
                    g_Wxo + c * HX_ * F_ + mb * 64 * F_, 64, F_, L_, nullptr, 0);
    } else {                           // bo2 = beq@Wzo + bo
        const int c = t - 18;
        small_gemmK(g_beq + c * L_, L_, g_Wzo + c * L_ * F_, F_,
                    g_bo2 + c * F_, 1, F_, L_, g_bo + c * F_, 0);
    }
}

// fold stage 4: fold x_phi's Wx into the x->PI / x->PO paths (12 CTAs)
__global__ void __launch_bounds__(256) kernelF4(
    const float* __restrict__ Wx, const float* __restrict__ bx) {
    const int t = blockIdx.x;
    if (t < 6) {                       // WxI = Wx @ Wihq (K=128), M=64 blocks
        const int c = t >> 1, mb = t & 1;
        small_gemmK(Wx + (size_t)c * F_ * HX_ + mb * 64 * HX_, HX_,
                    g_Wihq + (size_t)c * HX_ * H_, H_,
                    g_WxI + (size_t)c * F_ * H_ + mb * 64 * H_, 64, H_, HX_,
                    nullptr, 0);
    } else if (t < 9) {                // WxO = Wx @ Wxo (K=128)
        const int c = t - 6;
        small_gemmK(Wx + (size_t)c * F_ * HX_, HX_,
                    g_Wxo + (size_t)c * HX_ * F_, F_,
                    g_WxO + (size_t)c * F_ * F_, F_, F_, HX_, nullptr, 0);
    } else {                           // bihq2, bo3
        const int c = t - 9;
        small_gemmK(bx + c * HX_, HX_, g_Wihq + (size_t)c * HX_ * H_, H_,
                    g_bihq2 + c * H_, 1, H_, HX_, g_bihq + c * H_, 0);
        small_gemmK(bx + c * HX_, HX_, g_Wxo + (size_t)c * HX_ * F_, F_,
                    g_bo3 + c * F_, 1, F_, HX_, g_bo2 + c * F_, 0);
    }
}

// ===========================================================================
// Parallel GEMM machinery (kernels A and C)
// ===========================================================================
__device__ __forceinline__ void gemm64(const float* __restrict__ As,
                                       const float* __restrict__ Ws,
                                       int k0, float acc[8][8]) {
    const int tc = threadIdx.x & 15;
    const int tr = threadIdx.x >> 4;
    const float* ap = As + tr * 8 * 128 + k0;
    const float* bp = Ws + tc * 8;
#pragma unroll 4
    for (int k = 0; k < 64; ++k) {
        const float4 b0 = *reinterpret_cast<const float4*>(bp + k * 128);
        const float4 b1 = *reinterpret_cast<const float4*>(bp + k * 128 + 4);
        float a[8];
#pragma unroll
        for (int i = 0; i < 8; ++i) a[i] = ap[i * 128 + k];
        const float bv[8] = {b0.x, b0.y, b0.z, b0.w, b1.x, b1.y, b1.z, b1.w};
#pragma unroll
        for (int i = 0; i < 8; ++i)
#pragma unroll
            for (int j = 0; j < 8; ++j)
                acc[i][j] = fmaf(a[i], bv[j], acc[i][j]);
    }
}

// Load a 128x128 fp32 tile (row stride ld) into smem
__device__ __forceinline__ void load_tile(float* dst, const float* __restrict__ src,
                                          int ld) {
    for (int idx = threadIdx.x; idx < 128 * 32; idx += 256) {
        const int r = idx >> 5;
        const int c4 = idx & 31;
        reinterpret_cast<float4*>(dst)[(r << 5) + c4] =
            *reinterpret_cast<const float4*>(src + (size_t)r * ld + (c4 << 2));
    }
}

// Load a 64x128 fp32 slab (row stride ld) into smem
__device__ __forceinline__ void load_half(float* dst, const float* __restrict__ src,
                                          int ld) {
    for (int idx = threadIdx.x; idx < 64 * 32; idx += 256) {
        const int r = idx >> 5;
        const int c4 = idx & 31;
        reinterpret_cast<float4*>(dst)[(r << 5) + c4] =
            *reinterpret_cast<const float4*>(src + (size_t)r * ld + (c4 << 2));
    }
}

__device__ __forceinline__ void zero_acc(float acc[8][8]) {
#pragma unroll
    for (int i = 0; i < 8; ++i)
#pragma unroll
        for (int j = 0; j < 8; ++j) acc[i][j] = 0.f;
}

// full 128-deep GEMM as two 64-row slabs streamed through Ws
__device__ __forceinline__ void gemm128_slabs(const float* As, float* Ws,
                                              const float* __restrict__ W,
                                              int ldw, float acc[8][8]) {
#pragma unroll
    for (int h = 0; h < 2; ++h) {
        load_half(Ws, W + (size_t)(h * 64) * ldw, ldw);
        __syncthreads();
        gemm64(As, Ws, h * 64, acc);
        __syncthreads();
    }
}

// ---------------------------------------------------------------------------
// Kernel A: PO = x@WxO + bo3; PI = x@WxI + bihq2   (3 gemm units per tile)
// grid (4 btiles, T, C), 256 threads, 96KB dynamic smem
// ---------------------------------------------------------------------------
__global__ void __launch_bounds__(256, 2) kernelA(const float* __restrict__ x) {
    extern __shared__ float sm[];
    float* As = sm;                // 128x128
    float* Ws = sm + 128 * 128;    // 8192-float slab
    const int bt = blockIdx.x, t = blockIdx.y, c = blockIdx.z;
    const long rg0 = ((long)(c * T_ + t) * B_ + bt * 128);
    const int tc = threadIdx.x & 15, tr = threadIdx.x >> 4;

    load_tile(As, x + rg0 * F_, F_);   // ordered by sync inside gemm128_slabs

    float acc[8][8];

    // PO = x @ WxO + bo3
    zero_acc(acc);
    gemm128_slabs(As, Ws, g_WxO + (size_t)c * F_ * F_, F_, acc);
#pragma unroll
    for (int i = 0; i < 8; ++i)
#pragma unroll
        for (int j = 0; j < 8; ++j)
            g_PO[(rg0 + tr * 8 + i) * F_ + tc * 8 + j] =
                acc[i][j] + g_bo3[c * F_ + tc * 8 + j];

    // PI = x @ WxI + bihq2 (two 128-col halves)
#pragma unroll
    for (int half = 0; half < 2; ++half) {
        zero_acc(acc);
        gemm128_slabs(As, Ws, g_WxI + (size_t)c * F_ * H_ + half * 128, H_, acc);
#pragma unroll
        for (int i = 0; i < 8; ++i)
#pragma unroll
            for (int j = 0; j < 8; ++j) {
                const int n = half * 128 + tc * 8 + j;
                g_PI[(rg0 + tr * 8 + i) * H_ + n] =
                    acc[i][j] + g_bihq2[c * H_ + n];
            }
    }
}

// ===========================================================================
// Kernel B: the pure recurrence: h' = tanh(PI + h@Whh2). One GEMM per step.
// p=0 weight partition (rows 0..63) staged in smem -> 25% less L2 traffic.
// ===========================================================================
__device__ __forceinline__ float fast_tanh(float x) {
    // tanh(x) = 1 - 2/(exp(2x)+1); safe at +/-inf, abs err ~1e-7
    const float e = __expf(2.f * x);
    return 1.f - __fdividef(2.f, e + 1.f);
}

// K=256, N=256 (G=64, P=4, Ks=64); p==0 reads weights from smem copy.
__device__ __forceinline__ void mm4s(const float* __restrict__ Wg,
                                     const float* __restrict__ Wsm,
                                     const float* __restrict__ a_s,
                                     float4 acc[RMAX_]) {
    constexpr int G = 64;   // N/4
    constexpr int Ks = 64;  // K/P
    const int g = threadIdx.x % G;
    const int p = threadIdx.x / G;
    // uniform per warp (warps are 32 threads; G=64 aligned)
    const float4* wp = (p == 0)
        ? reinterpret_cast<const float4*>(Wsm) + g
        : reinterpret_cast<const float4*>(Wg) + (size_t)(p * Ks) * G + g;
    const float* ap = a_s + p * Ks;

    float4 w0 = wp[0 * G], w1 = wp[1 * G], w2 = wp[2 * G], w3 = wp[3 * G];
#pragma unroll 1
    for (int k = 0; k < Ks; k += 4) {
        float4 n0, n1, n2, n3;
        if (k + 4 < Ks) {
            n0 = wp[(k + 4) * G];
            n1 = wp[(k + 5) * G];
            n2 = wp[(k + 6) * G];
            n3 = wp[(k + 7) * G];
        }
#pragma unroll
        for (int r = 0; r < RMAX_; ++r) {
            const float4 a = *reinterpret_cast<const float4*>(ap + r * 256 + k);
            acc[r].x = fmaf(a.x, w0.x, acc[r].x);
            acc[r].y = fmaf(a.x, w0.y, acc[r].y);
            acc[r].z = fmaf(a.x, w0.z, acc[r].z);
            acc[r].w = fmaf(a.x, w0.w, acc[r].w);
            acc[r].x = fmaf(a.y, w1.x, acc[r].x);
            acc[r].y = fmaf(a.y, w1.y, acc[r].y);
            acc[r].z = fmaf(a.y, w1.z, acc[r].z);
            acc[r].w = fmaf(a.y, w1.w, acc[r].w);
            acc[r].x = fmaf(a.z, w2.x, acc[r].x);
            acc[r].y = fmaf(a.z, w2.y, acc[r].y);
            acc[r].z = fmaf(a.z, w2.z, acc[r].z);
            acc[r].w = fmaf(a.z, w2.w, acc[r].w);
            acc[r].x = fmaf(a.w, w3.x, acc[r].x);
            acc[r].y = fmaf(a.w, w3.y, acc[r].y);
            acc[r].z = fmaf(a.w, w3.z, acc[r].z);
            acc[r].w = fmaf(a.w, w3.w, acc[r].w);
        }
        w0 = n0; w1 = n1; w2 = n2; w3 = n3;
    }
}

__device__ __forceinline__ void store_scr256(float* __restrict__ scr,
                                             const float4 acc[RMAX_]) {
    const int g = threadIdx.x % 64;
    const int p = threadIdx.x / 64;
#pragma unroll
    for (int r = 0; r < RMAX_; ++r)
        *reinterpret_cast<float4*>(scr + (size_t)(p * RMAX_ + r) * 256 + 4 * g) = acc[r];
}

__device__ __forceinline__ void zero4(float4 acc[RMAX_]) {
#pragma unroll
    for (int r = 0; r < RMAX_; ++r) acc[r] = make_float4(0.f, 0.f, 0.f, 0.f);
}

__global__ void __launch_bounds__(256, 2) kernelB(const float* __restrict__ h0) {
    // dynamic smem: hs[1536] | scr2[6144] | wsm[16384]  -> 94 KB
    extern __shared__ float smb[];
    float* hs   = smb;
    float* scr2 = smb + RMAX_ * H_;
    float* wsm  = scr2 + 4 * RMAX_ * 256;

    const int c = blockIdx.y;
    // overlapping coverage: 86 CTAs x 6 rows = 516 >= 512; duplicated rows
    // compute bit-identical values, duplicate global stores are benign.
    const int r0 = (blockIdx.x * (B_ - RMAX_)) / (NB_ - 1);
    const int tid = threadIdx.x;

    const float* Whh2 = g_Whh2 + (size_t)c * H_ * H_;

    for (int idx = tid; idx < RMAX_ * H_; idx += 256)
        hs[idx] = h0[(size_t)(c * B_ + r0) * H_ + idx];
    // stage rows 0..63 of Whh2 (the p=0 k-partition) into smem
    for (int idx = tid; idx < 64 * 256 / 4; idx += 256)
        reinterpret_cast<float4*>(wsm)[idx] =
            reinterpret_cast<const float4*>(Whh2)[idx];
    __syncthreads();

    float4 acc[RMAX_];

    long rg0 = (long)c * T_ * B_ + r0;
    for (int t = 0; t < T_; ++t, rg0 += B_) {
        // prefetch this step's PI into registers (overlaps with FMAs below)
        float pip[RMAX_];
#pragma unroll
        for (int j = 0; j < RMAX_; ++j)
            pip[j] = g_PI[rg0 * H_ + j * 256 + tid];

        zero4(acc);
        mm4s(Whh2, wsm, hs, acc);          // h partials (P=4; p0 from smem)
        store_scr256(scr2, acc);
        // store Hs[t] = h (pre-update) while partials land
        for (int idx = tid; idx < RMAX_ * H_ / 4; idx += 256)
            reinterpret_cast<float4*>(&g_Hs[rg0 * H_])[idx] =
                reinterpret_cast<const float4*>(hs)[idx];
        __syncthreads();

        // reduce 4 partials + PI -> tanh -> hs (1536 outputs)
#pragma unroll
        for (int j = 0; j < RMAX_; ++j) {
            const int idx = j * 256 + tid;
            const int r = idx >> 8;
            const int n = idx & 255;
            float s = pip[j];
#pragma unroll
            for (int p = 0; p < 4; ++p)
                s += scr2[(size_t)(p * RMAX_ + r) * 256 + n];
            hs[idx] = fast_tanh(s);
        }
        __syncthreads();
    }
}

// ---------------------------------------------------------------------------
// Kernel C: out = PO + Hs@Who2
// grid (4 btiles, T, C), 256 threads, 96KB dynamic smem
// ---------------------------------------------------------------------------
__global__ void __launch_bounds__(256, 2) kernelC(float* __restrict__ out) {
    extern __shared__ float sm[];
    float* As = sm;
    float* Ws = sm + 128 * 128;
    const int bt = blockIdx.x, t = blockIdx.y, c = blockIdx.z;
    const long rg0 = ((long)(c * T_ + t) * B_ + bt * 128);
    const int tc = threadIdx.x & 15, tr = threadIdx.x >> 4;

    float acc[8][8];
    zero_acc(acc);

    // h part: two 128-row slices of Who2 (K=256 total)
    load_tile(As, g_Hs + rg0 * H_, H_);
    gemm128_slabs(As, Ws, g_Who2 + (size_t)c * H_ * F_, F_, acc);
    load_tile(As, g_Hs + rg0 * H_ + 128, H_);
    gemm128_slabs(As, Ws, g_Who2 + (size_t)c * H_ * F_ + 128 * F_, F_, acc);

#pragma unroll
    for (int i = 0; i < 8; ++i)
#pragma unroll
        for (int j = 0; j < 8; ++j) {
            const long o = (rg0 + tr * 8 + i) * F_ + tc * 8 + j;
            out[o] = acc[i][j] + g_PO[o];
        }
}

// ---------------------------------------------------------------------------
extern "C" void kernel_launch(void* const* d_in, const int* in_sizes, int n_in,
                              void* d_out, int out_size) {
    (void)in_sizes; (void)n_in; (void)out_size;
    const float* x        = (const float*)d_in[0];
    const float* phi_x_W  = (const float*)d_in[1];
    const float* phi_x_b  = (const float*)d_in[2];
    const float* enc_W    = (const float*)d_in[3];
    const float* enc_b    = (const float*)d_in[4];
    const float* enc_mu_W = (const float*)d_in[5];
    const float* enc_mu_b = (const float*)d_in[6];
    const float* phi_z_W  = (const float*)d_in[7];
    const float* phi_z_b  = (const float*)d_in[8];
    const float* dec_W    = (const float*)d_in[9];
    const float* dec_b    = (const float*)d_in[10];
    const float* dec_mu_W = (const float*)d_in[11];
    const float* dec_mu_b = (const float*)d_in[12];
    const float* rnn_Wih  = (const float*)d_in[13];
    const float* rnn_Whh  = (const float*)d_in[14];
    const float* rnn_bih  = (const float*)d_in[15];
    const float* rnn_bhh  = (const float*)d_in[16];
    const float* h0       = (const float*)d_in[17];
    float* out = (float*)d_out;

    const size_t smemAC = (128 * 128 + 64 * 128) * sizeof(float);  // 96 KB
    const size_t smemB  = (RMAX_ * H_ + 4 * RMAX_ * 256 + 64 * 256)
                          * sizeof(float);                          // 94 KB
    cudaFuncSetAttribute(kernelA, cudaFuncAttributeMaxDynamicSharedMemorySize,
                         (int)smemAC);
    cudaFuncSetAttribute(kernelB, cudaFuncAttributeMaxDynamicSharedMemorySize,
                         (int)smemB);
    cudaFuncSetAttribute(kernelC, cudaFuncAttributeMaxDynamicSharedMemorySize,
                         (int)smemAC);

    kernelF1<<<29, 256>>>(enc_W, enc_b, enc_mu_W, enc_mu_b, phi_z_W, phi_z_b,
                          dec_W, dec_b, rnn_Wih);
    kernelF2<<<39, 256>>>(dec_W, dec_mu_W, dec_mu_b, rnn_Whh, rnn_Wih,
                          rnn_bih, rnn_bhh);
    kernelF3<<<21, 256>>>();
    kernelF4<<<12, 256>>>(phi_x_W, phi_x_b);
    kernelA<<<dim3(4, T_, C_), 256, smemAC>>>(x);
    kernelB<<<dim3(NB_, C_), 256, smemB>>>(h0);
    kernelC<<<dim3(4, T_, C_), 256, smemAC>>>(out);
}

// round 12
// speedup vs baseline: 1.4570x; 1.0482x over previous
#include <cuda_runtime.h>
#include <math.h>

// Problem dims
#define C_   3
#define T_   100
#define B_   512
#define F_   128
#define HX_  128
#define HZ_  128
#define H_   256
#define EH_  128
#define L_   64

#define NB_   86   // CTAs per channel (86*6=516 >= 512; 258 CTAs, 1 wave @ 2/SM)
#define RMAX_ 6    // rows per CTA

// ---- big activations scratch ----
__device__ float g_PI[(size_t)C_ * T_ * B_ * H_];   // x@WxI + bihq2
__device__ float g_PO[(size_t)C_ * T_ * B_ * F_];   // x@WxO + bo3
__device__ float g_Hs[(size_t)C_ * T_ * B_ * H_];   // h at step input

// ---- folded weights (computed on-device each run; tiny) ----
__device__ float g_Weq[C_ * HX_ * L_];    // We_x @ Wqm              [128,64]/ch
__device__ float g_beq[C_ * L_];          // be@Wqm + bqm
__device__ float g_Wcomb[C_ * H_ * L_];   // We_h @ Wqm              [256,64]/ch
__device__ float g_Wihz[L_ * H_];         // Wzp @ Wih_z             [64,256]
__device__ float g_bihz[H_];              // bzp @ Wih_z
__device__ float g_Wdz[C_ * L_ * EH_];    // Wzp @ Wd_z              [64,128]/ch
__device__ float g_bdz[C_ * EH_];         // bzp@Wd_z + bd
__device__ float g_Wzo[C_ * L_ * F_];     // Wdz @ Wpm               [64,128]/ch
__device__ float g_Who[C_ * H_ * F_];     // Wd_h @ Wpm              [256,128]/ch
__device__ float g_bo[C_ * F_];           // bdz@Wpm + bpm
__device__ float g_Whh2[C_ * H_ * H_];    // Whh + Wcomb@Wihz        [256,256]/ch
__device__ float g_Wihq[C_ * HX_ * H_];   // Wih_x + Weq@Wihz        [128,256]/ch
__device__ float g_bihq[C_ * H_];         // bih+bhh+bihz + beq@Wihz
__device__ float g_Who2[C_ * H_ * F_];    // Who + Wcomb@Wzo         [256,128]/ch
__device__ float g_Wxo[C_ * HX_ * F_];    // Weq @ Wzo               [128,128]/ch
__device__ float g_bo2[C_ * F_];          // beq@Wzo + bo
__device__ float g_WxI[C_ * F_ * H_];     // Wx @ Wihq               [128,256]/ch
__device__ float g_bihq2[C_ * H_];        // bx@Wihq + bihq
__device__ float g_WxO[C_ * F_ * F_];     // Wx @ Wxo                [128,128]/ch
__device__ float g_bo3[C_ * F_];          // bx@Wxo + bo2

// ===========================================================================
// small GEMM block for weight folding: out[M,N] (ld ldo) = A[M,K]@Bm[K,N] (+addm)
// 4x4 register tile per thread; N multiple of 4; M%4 via scalar remainder.
// ===========================================================================
__device__ __forceinline__ void small_gemmK(const float* __restrict__ A, int lda,
                                            const float* __restrict__ Bm, int ldb,
                                            float* __restrict__ out, int ldo,
                                            int M, int N, int K,
                                            const float* __restrict__ addm,
                                            int ldam) {
    const int M4 = M >> 2;
    const int Nq = N >> 2;
    for (int idx = threadIdx.x; idx < M4 * Nq; idx += 256) {
        const int mg = idx / Nq, ng = idx % Nq;
        const int m = mg * 4, n = ng * 4;
        float4 s0, s1, s2, s3;
        if (addm) {
            s0 = *reinterpret_cast<const float4*>(addm + (size_t)(m + 0) * ldam + n);
            s1 = *reinterpret_cast<const float4*>(addm + (size_t)(m + 1) * ldam + n);
            s2 = *reinterpret_cast<const float4*>(addm + (size_t)(m + 2) * ldam + n);
            s3 = *reinterpret_cast<const float4*>(addm + (size_t)(m + 3) * ldam + n);
        } else {
            s0 = s1 = s2 = s3 = make_float4(0.f, 0.f, 0.f, 0.f);
        }
        const float* a0 = A + (size_t)(m + 0) * lda;
        const float* a1 = A + (size_t)(m + 1) * lda;
        const float* a2 = A + (size_t)(m + 2) * lda;
        const float* a3 = A + (size_t)(m + 3) * lda;
        const float* b = Bm + n;
#pragma unroll 4
        for (int k = 0; k < K; ++k) {
            const float4 bv = *reinterpret_cast<const float4*>(b + (size_t)k * ldb);
            const float v0 = a0[k], v1 = a1[k], v2 = a2[k], v3 = a3[k];
            s0.x = fmaf(v0, bv.x, s0.x); s0.y = fmaf(v0, bv.y, s0.y);
            s0.z = fmaf(v0, bv.z, s0.z); s0.w = fmaf(v0, bv.w, s0.w);
            s1.x = fmaf(v1, bv.x, s1.x); s1.y = fmaf(v1, bv.y, s1.y);
            s1.z = fmaf(v1, bv.z, s1.z); s1.w = fmaf(v1, bv.w, s1.w);
            s2.x = fmaf(v2, bv.x, s2.x); s2.y = fmaf(v2, bv.y, s2.y);
            s2.z = fmaf(v2, bv.z, s2.z); s2.w = fmaf(v2, bv.w, s2.w);
            s3.x = fmaf(v3, bv.x, s3.x); s3.y = fmaf(v3, bv.y, s3.y);
            s3.z = fmaf(v3, bv.z, s3.z); s3.w = fmaf(v3, bv.w, s3.w);
        }
        *reinterpret_cast<float4*>(out + (size_t)(m + 0) * ldo + n) = s0;
        *reinterpret_cast<float4*>(out + (size_t)(m + 1) * ldo + n) = s1;
        *reinterpret_cast<float4*>(out + (size_t)(m + 2) * ldo + n) = s2;
        *reinterpret_cast<float4*>(out + (size_t)(m + 3) * ldo + n) = s3;
    }
    // remainder rows (e.g. M==1 bias tasks)
    const int mrem0 = M4 * 4;
    for (int idx = threadIdx.x; idx < (M - mrem0) * N; idx += 256) {
        const int m = mrem0 + idx / N, n = idx % N;
        float s = addm ? addm[(size_t)m * ldam + n] : 0.f;
        const float* a = A + (size_t)m * lda;
        const float* b = Bm + n;
#pragma unroll 4
        for (int k = 0; k < K; ++k) s = fmaf(a[k], b[(size_t)k * ldb], s);
        out[(size_t)m * ldo + n] = s;
    }
}

// fold stage 1 (35 CTAs, 64x64 blocks)
__global__ void __launch_bounds__(256) kernelF1(
    const float* __restrict__ We, const float* __restrict__ be,
    const float* __restrict__ Wqm, const float* __restrict__ bqm,
    const float* __restrict__ Wzp, const float* __restrict__ bzp,
    const float* __restrict__ Wd, const float* __restrict__ bd,
    const float* __restrict__ Wih) {
    const int t = blockIdx.x;
    if (t < 6) {                       // Weq = We_x@Wqm   [128,64] (2 mblk)
        const int c = t >> 1, mb = t & 1;
        small_gemmK(We + (size_t)c * 384 * EH_ + mb * 64 * EH_, EH_,
                    Wqm + (size_t)c * EH_ * L_, L_,
                    g_Weq + c * HX_ * L_ + mb * 64 * L_, L_, 64, L_, EH_,
                    nullptr, 0);
    } else if (t < 18) {               // Wcomb = We_h@Wqm [256,64] (4 mblk)
        const int u = t - 6, c = u >> 2, mb = u & 3;
        small_gemmK(We + (size_t)c * 384 * EH_ + (128 + mb * 64) * EH_, EH_,
                    Wqm + (size_t)c * EH_ * L_, L_,
                    g_Wcomb + c * H_ * L_ + mb * 64 * L_, L_, 64, L_, EH_,
                    nullptr, 0);
    } else if (t < 24) {               // Wdz = Wzp@Wd_z [64,128] (2 nblk)
        const int u = t - 18, c = u >> 1, nb = u & 1;
        small_gemmK(Wzp, HZ_, Wd + (size_t)c * 384 * EH_ + nb * 64, EH_,
                    g_Wdz + c * L_ * EH_ + nb * 64, EH_, L_, 64, HZ_,
                    nullptr, 0);
    } else if (t < 28) {               // Wihz = Wzp@Wih_z [64,256] (4 nblk)
        const int nb = t - 24;
        small_gemmK(Wzp, HZ_, Wih + 128 * H_ + nb * 64, H_,
                    g_Wihz + nb * 64, H_, L_, 64, HZ_, nullptr, 0);
    } else if (t < 31) {               // beq = be@Wqm + bqm
        const int c = t - 28;
        small_gemmK(be + c * EH_, EH_, Wqm + (size_t)c * EH_ * L_, L_,
                    g_beq + c * L_, L_, 1, L_, EH_, bqm + c * L_, 0);
    } else if (t < 34) {               // bdz = bzp@Wd_z + bd
        const int c = t - 31;
        small_gemmK(bzp, HZ_, Wd + (size_t)c * 384 * EH_, EH_,
                    g_bdz + c * EH_, EH_, 1, EH_, HZ_, bd + c * EH_, 0);
    } else {                           // bihz = bzp@Wih_z
        small_gemmK(bzp, HZ_, Wih + 128 * H_, H_, g_bihz, H_, 1, H_, HZ_,
                    nullptr, 0);
    }
}

// fold stage 2 (108 CTAs, 64x64 blocks)
__global__ void __launch_bounds__(256) kernelF2(
    const float* __restrict__ Wd, const float* __restrict__ Wpm,
    const float* __restrict__ bpm, const float* __restrict__ Whh,
    const float* __restrict__ Wih, const float* __restrict__ bih,
    const float* __restrict__ bhh) {
    const int t = blockIdx.x;
    if (t < 6) {                       // Wzo = Wdz@Wpm [64,128] (2 nblk)
        const int c = t >> 1, nb = t & 1;
        small_gemmK(g_Wdz + c * L_ * EH_, EH_,
                    Wpm + (size_t)c * EH_ * F_ + nb * 64, F_,
                    g_Wzo + c * L_ * F_ + nb * 64, F_, L_, 64, EH_, nullptr, 0);
    } else if (t < 30) {               // Who = Wd_h@Wpm [256,128] (4m x 2n)
        const int u = t - 6, c = u >> 3, r = u & 7, mb = r >> 1, nb = r & 1;
        small_gemmK(Wd + (size_t)c * 384 * EH_ + (128 + mb * 64) * EH_, EH_,
                    Wpm + (size_t)c * EH_ * F_ + nb * 64, F_,
                    g_Who + c * H_ * F_ + mb * 64 * F_ + nb * 64, F_,
                    64, 64, EH_, nullptr, 0);
    } else if (t < 33) {               // bo = bdz@Wpm + bpm
        const int c = t - 30;
        small_gemmK(g_bdz + c * EH_, EH_, Wpm + (size_t)c * EH_ * F_, F_,
                    g_bo + c * F_, F_, 1, F_, EH_, bpm + c * F_, 0);
    } else if (t < 81) {               // Whh2 = Whh + Wcomb@Wihz (4m x 4n, K=64)
        const int u = t - 33, c = u >> 4, r = u & 15, mb = r >> 2, nb = r & 3;
        small_gemmK(g_Wcomb + c * H_ * L_ + mb * 64 * L_, L_,
                    g_Wihz + nb * 64, H_,
                    g_Whh2 + (size_t)c * H_ * H_ + mb * 64 * H_ + nb * 64, H_,
                    64, 64, L_, Whh + (size_t)mb * 64 * H_ + nb * 64, H_);
    } else if (t < 105) {              // Wihq = Wih_x + Weq@Wihz (2m x 4n, K=64)
        const int u = t - 81, c = u >> 3, r = u & 7, mb = r >> 2, nb = r & 3;
        small_gemmK(g_Weq + c * HX_ * L_ + mb * 64 * L_, L_,
                    g_Wihz + nb * 64, H_,
                    g_Wihq + (size_t)c * HX_ * H_ + mb * 64 * H_ + nb * 64, H_,
                    64, 64, L_, Wih + (size_t)mb * 64 * H_ + nb * 64, H_);
    } else {                           // bihq = bih+bhh+bihz + beq@Wihz
        const int c = t - 105;
        for (int n = threadIdx.x; n < H_; n += 256) {
            float s = bih[n] + bhh[n] + g_bihz[n];
            for (int l = 0; l < L_; ++l)
                s = fmaf(g_beq[c * L_ + l], g_Wihz[l * H_ + n], s);
            g_bihq[c * H_ + n] = s;
        }
    }
}

// fold stage 3 (39 CTAs)
__global__ void __launch_bounds__(256) kernelF3() {
    const int t = blockIdx.x;
    if (t < 24) {                      // Who2 = Who + Wcomb@Wzo (4m x 2n, K=64)
        const int c = t >> 3, r = t & 7, mb = r >> 1, nb = r & 1;
        small_gemmK(g_Wcomb + c * H_ * L_ + mb * 64 * L_, L_,
                    g_Wzo + c * L_ * F_ + nb * 64, F_,
                    g_Who2 + c * H_ * F_ + mb * 64 * F_ + nb * 64, F_,
                    64, 64, L_,
                    g_Who + c * H_ * F_ + mb * 64 * F_ + nb * 64, F_);
    } else if (t < 36) {               // Wxo = Weq@Wzo (2m x 2n, K=64)
        const int u = t - 24, c = u >> 2, r = u & 3, mb = r >> 1, nb = r & 1;
        small_gemmK(g_Weq + c * HX_ * L_ + mb * 64 * L_, L_,
                    g_Wzo + c * L_ * F_ + nb * 64, F_,
                    g_Wxo + c * HX_ * F_ + mb * 64 * F_ + nb * 64, F_,
                    64, 64, L_, nullptr, 0);
    } else {                           // bo2 = beq@Wzo + bo
        const int c = t - 36;
        small_gemmK(g_beq + c * L_, L_, g_Wzo + c * L_ * F_, F_,
                    g_bo2 + c * F_, F_, 1, F_, L_, g_bo + c * F_, 0);
    }
}

// fold stage 4 (39 CTAs)
__global__ void __launch_bounds__(256) kernelF4(
    const float* __restrict__ Wx, const float* __restrict__ bx) {
    const int t = blockIdx.x;
    if (t < 24) {                      // WxI = Wx@Wihq (2m x 4n, K=128)
        const int c = t >> 3, r = t & 7, mb = r >> 2, nb = r & 3;
        small_gemmK(Wx + (size_t)c * F_ * HX_ + mb * 64 * HX_, HX_,
                    g_Wihq + (size_t)c * HX_ * H_ + nb * 64, H_,
                    g_WxI + (size_t)c * F_ * H_ + mb * 64 * H_ + nb * 64, H_,
                    64, 64, HX_, nullptr, 0);
    } else if (t < 36) {               // WxO = Wx@Wxo (2m x 2n, K=128)
        const int u = t - 24, c = u >> 2, r = u & 3, mb = r >> 1, nb = r & 1;
        small_gemmK(Wx + (size_t)c * F_ * HX_ + mb * 64 * HX_, HX_,
                    g_Wxo + (size_t)c * HX_ * F_ + nb * 64, F_,
                    g_WxO + (size_t)c * F_ * F_ + mb * 64 * F_ + nb * 64, F_,
                    64, 64, HX_, nullptr, 0);
    } else {                           // bihq2, bo3
        const int c = t - 36;
        small_gemmK(bx + c * HX_, HX_, g_Wihq + (size_t)c * HX_ * H_, H_,
                    g_bihq2 + c * H_, H_, 1, H_, HX_, g_bihq + c * H_, 0);
        small_gemmK(bx + c * HX_, HX_, g_Wxo + (size_t)c * HX_ * F_, F_,
                    g_bo3 + c * F_, F_, 1, F_, HX_, g_bo2 + c * F_, 0);
    }
}

// ===========================================================================
// Parallel GEMM machinery (kernels A and C)
// ===========================================================================
__device__ __forceinline__ void gemm64(const float* __restrict__ As,
                                       const float* __restrict__ Ws,
                                       int k0, float acc[8][8]) {
    const int tc = threadIdx.x & 15;
    const int tr = threadIdx.x >> 4;
    const float* ap = As + tr * 8 * 128 + k0;
    const float* bp = Ws + tc * 8;
#pragma unroll 4
    for (int k = 0; k < 64; ++k) {
        const float4 b0 = *reinterpret_cast<const float4*>(bp + k * 128);
        const float4 b1 = *reinterpret_cast<const float4*>(bp + k * 128 + 4);
        float a[8];
#pragma unroll
        for (int i = 0; i < 8; ++i) a[i] = ap[i * 128 + k];
        const float bv[8] = {b0.x, b0.y, b0.z, b0.w, b1.x, b1.y, b1.z, b1.w};
#pragma unroll
        for (int i = 0; i < 8; ++i)
#pragma unroll
            for (int j = 0; j < 8; ++j)
                acc[i][j] = fmaf(a[i], bv[j], acc[i][j]);
    }
}

// Load a 128x128 fp32 tile (row stride ld) into smem
__device__ __forceinline__ void load_tile(float* dst, const float* __restrict__ src,
                                          int ld) {
    for (int idx = threadIdx.x; idx < 128 * 32; idx += 256) {
        const int r = idx >> 5;
        const int c4 = idx & 31;
        reinterpret_cast<float4*>(dst)[(r << 5) + c4] =
            *reinterpret_cast<const float4*>(src + (size_t)r * ld + (c4 << 2));
    }
}

// Load a 64x128 fp32 slab (row stride ld) into smem
__device__ __forceinline__ void load_half(float* dst, const float* __restrict__ src,
                                          int ld) {
    for (int idx = threadIdx.x; idx < 64 * 32; idx += 256) {
        const int r = idx >> 5;
        const int c4 = idx & 31;
        reinterpret_cast<float4*>(dst)[(r << 5) + c4] =
            *reinterpret_cast<const float4*>(src + (size_t)r * ld + (c4 << 2));
    }
}

__device__ __forceinline__ void zero_acc(float acc[8][8]) {
#pragma unroll
    for (int i = 0; i < 8; ++i)
#pragma unroll
        for (int j = 0; j < 8; ++j) acc[i][j] = 0.f;
}

// full 128-deep GEMM as two 64-row slabs streamed through Ws
__device__ __forceinline__ void gemm128_slabs(const float* As, float* Ws,
                                              const float* __restrict__ W,
                                              int ldw, float acc[8][8]) {
#pragma unroll
    for (int h = 0; h < 2; ++h) {
        load_half(Ws, W + (size_t)(h * 64) * ldw, ldw);
        __syncthreads();
        gemm64(As, Ws, h * 64, acc);
        __syncthreads();
    }
}

// ---------------------------------------------------------------------------
// Kernel A: PO = x@WxO + bo3; PI = x@WxI + bihq2   (3 gemm units per tile)
// grid (4 btiles, T, C), 256 threads, 96KB dynamic smem
// ---------------------------------------------------------------------------
__global__ void __launch_bounds__(256, 2) kernelA(const float* __restrict__ x) {
    extern __shared__ float sm[];
    float* As = sm;                // 128x128
    float* Ws = sm + 128 * 128;    // 8192-float slab
    const int bt = blockIdx.x, t = blockIdx.y, c = blockIdx.z;
    const long rg0 = ((long)(c * T_ + t) * B_ + bt * 128);
    const int tc = threadIdx.x & 15, tr = threadIdx.x >> 4;

    load_tile(As, x + rg0 * F_, F_);   // ordered by sync inside gemm128_slabs

    float acc[8][8];

    // PO = x @ WxO + bo3
    zero_acc(acc);
    gemm128_slabs(As, Ws, g_WxO + (size_t)c * F_ * F_, F_, acc);
#pragma unroll
    for (int i = 0; i < 8; ++i)
#pragma unroll
        for (int j = 0; j < 8; ++j)
            g_PO[(rg0 + tr * 8 + i) * F_ + tc * 8 + j] =
                acc[i][j] + g_bo3[c * F_ + tc * 8 + j];

    // PI = x @ WxI + bihq2 (two 128-col halves)
#pragma unroll
    for (int half = 0; half < 2; ++half) {
        zero_acc(acc);
        gemm128_slabs(As, Ws, g_WxI + (size_t)c * F_ * H_ + half * 128, H_, acc);
#pragma unroll
        for (int i = 0; i < 8; ++i)
#pragma unroll
            for (int j = 0; j < 8; ++j) {
                const int n = half * 128 + tc * 8 + j;
                g_PI[(rg0 + tr * 8 + i) * H_ + n] =
                    acc[i][j] + g_bihq2[c * H_ + n];
            }
    }
}

// ===========================================================================
// Kernel B: the pure recurrence: h' = tanh(PI + h@Whh2). One GEMM per step.
// p=0 weight partition (rows 0..63) staged in smem -> 25% less L2 traffic.
// ===========================================================================
__device__ __forceinline__ float fast_tanh(float x) {
    // tanh(x) = 1 - 2/(exp(2x)+1); safe at +/-inf, abs err ~1e-7
    const float e = __expf(2.f * x);
    return 1.f - __fdividef(2.f, e + 1.f);
}

// K=256, N=256 (G=64, P=4, Ks=64); p==0 reads weights from smem copy.
__device__ __forceinline__ void mm4s(const float* __restrict__ Wg,
                                     const float* __restrict__ Wsm,
                                     const float* __restrict__ a_s,
                                     float4 acc[RMAX_]) {
    constexpr int G = 64;   // N/4
    constexpr int Ks = 64;  // K/P
    const int g = threadIdx.x % G;
    const int p = threadIdx.x / G;
    // uniform per warp (warps are 32 threads; G=64 aligned)
    const float4* wp = (p == 0)
        ? reinterpret_cast<const float4*>(Wsm) + g
        : reinterpret_cast<const float4*>(Wg) + (size_t)(p * Ks) * G + g;
    const float* ap = a_s + p * Ks;

    float4 w0 = wp[0 * G], w1 = wp[1 * G], w2 = wp[2 * G], w3 = wp[3 * G];
#pragma unroll 1
    for (int k = 0; k < Ks; k += 4) {
        float4 n0, n1, n2, n3;
        if (k + 4 < Ks) {
            n0 = wp[(k + 4) * G];
            n1 = wp[(k + 5) * G];
            n2 = wp[(k + 6) * G];
            n3 = wp[(k + 7) * G];
        }
#pragma unroll
        for (int r = 0; r < RMAX_; ++r) {
            const float4 a = *reinterpret_cast<const float4*>(ap + r * 256 + k);
            acc[r].x = fmaf(a.x, w0.x, acc[r].x);
            acc[r].y = fmaf(a.x, w0.y, acc[r].y);
            acc[r].z = fmaf(a.x, w0.z, acc[r].z);
            acc[r].w = fmaf(a.x, w0.w, acc[r].w);
            acc[r].x = fmaf(a.y, w1.x, acc[r].x);
            acc[r].y = fmaf(a.y, w1.y, acc[r].y);
            acc[r].z = fmaf(a.y, w1.z, acc[r].z);
            acc[r].w = fmaf(a.y, w1.w, acc[r].w);
            acc[r].x = fmaf(a.z, w2.x, acc[r].x);
            acc[r].y = fmaf(a.z, w2.y, acc[r].y);
            acc[r].z = fmaf(a.z, w2.z, acc[r].z);
            acc[r].w = fmaf(a.z, w2.w, acc[r].w);
            acc[r].x = fmaf(a.w, w3.x, acc[r].x);
            acc[r].y = fmaf(a.w, w3.y, acc[r].y);
            acc[r].z = fmaf(a.w, w3.z, acc[r].z);
            acc[r].w = fmaf(a.w, w3.w, acc[r].w);
        }
        w0 = n0; w1 = n1; w2 = n2; w3 = n3;
    }
}

__device__ __forceinline__ void store_scr256(float* __restrict__ scr,
                                             const float4 acc[RMAX_]) {
    const int g = threadIdx.x % 64;
    const int p = threadIdx.x / 64;
#pragma unroll
    for (int r = 0; r < RMAX_; ++r)
        *reinterpret_cast<float4*>(scr + (size_t)(p * RMAX_ + r) * 256 + 4 * g) = acc[r];
}

__device__ __forceinline__ void zero4(float4 acc[RMAX_]) {
#pragma unroll
    for (int r = 0; r < RMAX_; ++r) acc[r] = make_float4(0.f, 0.f, 0.f, 0.f);
}

__global__ void __launch_bounds__(256, 2) kernelB(const float* __restrict__ h0) {
    // dynamic smem: hs[1536] | scr2[6144] | wsm[16384]  -> 94 KB
    extern __shared__ float smb[];
    float* hs   = smb;
    float* scr2 = smb + RMAX_ * H_;
    float* wsm  = scr2 + 4 * RMAX_ * 256;

    const int c = blockIdx.y;
    // overlapping coverage: 86 CTAs x 6 rows = 516 >= 512; duplicated rows
    // compute bit-identical values, duplicate global stores are benign.
    const int r0 = (blockIdx.x * (B_ - RMAX_)) / (NB_ - 1);
    const int tid = threadIdx.x;

    const float* Whh2 = g_Whh2 + (size_t)c * H_ * H_;

    for (int idx = tid; idx < RMAX_ * H_; idx += 256)
        hs[idx] = h0[(size_t)(c * B_ + r0) * H_ + idx];
    // stage rows 0..63 of Whh2 (the p=0 k-partition) into smem
    for (int idx = tid; idx < 64 * 256 / 4; idx += 256)
        reinterpret_cast<float4*>(wsm)[idx] =
            reinterpret_cast<const float4*>(Whh2)[idx];
    __syncthreads();

    float4 acc[RMAX_];

    long rg0 = (long)c * T_ * B_ + r0;
    for (int t = 0; t < T_; ++t, rg0 += B_) {
        // prefetch this step's PI into registers (overlaps with FMAs below)
        float pip[RMAX_];
#pragma unroll
        for (int j = 0; j < RMAX_; ++j)
            pip[j] = g_PI[rg0 * H_ + j * 256 + tid];

        zero4(acc);
        mm4s(Whh2, wsm, hs, acc);          // h partials (P=4; p0 from smem)
        store_scr256(scr2, acc);
        // store Hs[t] = h (pre-update) while partials land
        for (int idx = tid; idx < RMAX_ * H_ / 4; idx += 256)
            reinterpret_cast<float4*>(&g_Hs[rg0 * H_])[idx] =
                reinterpret_cast<const float4*>(hs)[idx];
        __syncthreads();

        // reduce 4 partials + PI -> tanh -> hs (1536 outputs)
#pragma unroll
        for (int j = 0; j < RMAX_; ++j) {
            const int idx = j * 256 + tid;
            const int r = idx >> 8;
            const int n = idx & 255;
            float s = pip[j];
#pragma unroll
            for (int p = 0; p < 4; ++p)
                s += scr2[(size_t)(p * RMAX_ + r) * 256 + n];
            hs[idx] = fast_tanh(s);
        }
        __syncthreads();
    }
}

// ---------------------------------------------------------------------------
// Kernel C: out = PO + Hs@Who2
// grid (4 btiles, T, C), 256 threads, 96KB dynamic smem
// ---------------------------------------------------------------------------
__global__ void __launch_bounds__(256, 2) kernelC(float* __restrict__ out) {
    extern __shared__ float sm[];
    float* As = sm;
    float* Ws = sm + 128 * 128;
    const int bt = blockIdx.x, t = blockIdx.y, c = blockIdx.z;
    const long rg0 = ((long)(c * T_ + t) * B_ + bt * 128);
    const int tc = threadIdx.x & 15, tr = threadIdx.x >> 4;

    float acc[8][8];
    zero_acc(acc);

    // h part: two 128-row slices of Who2 (K=256 total)
    load_tile(As, g_Hs + rg0 * H_, H_);
    gemm128_slabs(As, Ws, g_Who2 + (size_t)c * H_ * F_, F_, acc);
    load_tile(As, g_Hs + rg0 * H_ + 128, H_);
    gemm128_slabs(As, Ws, g_Who2 + (size_t)c * H_ * F_ + 128 * F_, F_, acc);

#pragma unroll
    for (int i = 0; i < 8; ++i)
#pragma unroll
        for (int j = 0; j < 8; ++j) {
            const long o = (rg0 + tr * 8 + i) * F_ + tc * 8 + j;
            out[o] = acc[i][j] + g_PO[o];
        }
}

// ---------------------------------------------------------------------------
extern "C" void kernel_launch(void* const* d_in, const int* in_sizes, int n_in,
                              void* d_out, int out_size) {
    (void)in_sizes; (void)n_in; (void)out_size;
    const float* x        = (const float*)d_in[0];
    const float* phi_x_W  = (const float*)d_in[1];
    const float* phi_x_b  = (const float*)d_in[2];
    const float* enc_W    = (const float*)d_in[3];
    const float* enc_b    = (const float*)d_in[4];
    const float* enc_mu_W = (const float*)d_in[5];
    const float* enc_mu_b = (const float*)d_in[6];
    const float* phi_z_W  = (const float*)d_in[7];
    const float* phi_z_b  = (const float*)d_in[8];
    const float* dec_W    = (const float*)d_in[9];
    const float* dec_b    = (const float*)d_in[10];
    const float* dec_mu_W = (const float*)d_in[11];
    const float* dec_mu_b = (const float*)d_in[12];
    const float* rnn_Wih  = (const float*)d_in[13];
    const float* rnn_Whh  = (const float*)d_in[14];
    const float* rnn_bih  = (const float*)d_in[15];
    const float* rnn_bhh  = (const float*)d_in[16];
    const float* h0       = (const float*)d_in[17];
    float* out = (float*)d_out;

    const size_t smemAC = (128 * 128 + 64 * 128) * sizeof(float);  // 96 KB
    const size_t smemB  = (RMAX_ * H_ + 4 * RMAX_ * 256 + 64 * 256)
                          * sizeof(float);                          // 94 KB
    cudaFuncSetAttribute(kernelA, cudaFuncAttributeMaxDynamicSharedMemorySize,
                         (int)smemAC);
    cudaFuncSetAttribute(kernelB, cudaFuncAttributeMaxDynamicSharedMemorySize,
                         (int)smemB);
    cudaFuncSetAttribute(kernelC, cudaFuncAttributeMaxDynamicSharedMemorySize,
                         (int)smemAC);

    kernelF1<<<35, 256>>>(enc_W, enc_b, enc_mu_W, enc_mu_b, phi_z_W, phi_z_b,
                          dec_W, dec_b, rnn_Wih);
    kernelF2<<<108, 256>>>(dec_W, dec_mu_W, dec_mu_b, rnn_Whh, rnn_Wih,
                           rnn_bih, rnn_bhh);
    kernelF3<<<39, 256>>>();
    kernelF4<<<39, 256>>>(phi_x_W, phi_x_b);
    kernelA<<<dim3(4, T_, C_), 256, smemAC>>>(x);
    kernelB<<<dim3(NB_, C_), 256, smemB>>>(h0);
    kernelC<<<dim3(4, T_, C_), 256, smemAC>>>(out);
}